// round 3
// baseline (speedup 1.0000x reference)
#include <cuda_runtime.h>

#define NN 100000
#define EE 1600000
#define HID 128
#define FEAT 16
#define INDIM 20
#define NTYPE 4
#define NREL 3
#define LNEPS 1e-5f

// ---------------- scratch (static device globals; no allocation) ----------------
__device__ float g_x[(size_t)NN * HID];
__device__ float g_y[NREL][(size_t)NN * HID];
__device__ float g_xl[(size_t)NN * HID];
__device__ float g_agg[(size_t)NN * HID];
__device__ int   g_deg[NN];
__device__ float g_pooled[HID];

// ---------------- small utility kernels ----------------
__global__ void k_zero_misc() {
    int i = blockIdx.x * blockDim.x + threadIdx.x;
    if (i < NN) g_deg[i] = 0;
    if (i < HID) g_pooled[i] = 0.f;
}

__global__ void k_zero_agg() {
    size_t n = (size_t)NN * HID / 4;
    float4* p = (float4*)g_agg;
    size_t st = (size_t)gridDim.x * blockDim.x;
    for (size_t i = (size_t)blockIdx.x * blockDim.x + threadIdx.x; i < n; i += st)
        p[i] = make_float4(0.f, 0.f, 0.f, 0.f);
}

__global__ void k_deg(const int* __restrict__ dst) {
    int st = gridDim.x * blockDim.x;
    for (int i = blockIdx.x * blockDim.x + threadIdx.x; i < EE; i += st)
        atomicAdd(&g_deg[dst[i]], 1);
}

// ---------------- encoder: per-type 2-layer MLP ----------------
// block = 256 threads, 32 nodes. dyn smem:
//  sW2[16384] | sW1[10240] | sh1[4096] | sb1[512] | sb2[512] | sraw[640] | stype[32]
#define ENC_SMEM_BYTES (129664)
__global__ __launch_bounds__(256) void k_enc(
    const int* __restrict__ z, const float* __restrict__ sd,
    const float* __restrict__ dff, const float* __restrict__ cond,
    const float* __restrict__ mult, const int* __restrict__ ntype,
    const float* __restrict__ zemb,
    const float* __restrict__ W1, const float* __restrict__ b1,
    const float* __restrict__ W2, const float* __restrict__ b2)
{
    extern __shared__ __align__(16) float sm[];
    float* sW2  = sm;                 // 128*128
    float* sW1  = sm + 16384;         // 4*20*128
    float* sh1  = sW1 + 10240;        // 32*128
    float* sb1  = sh1 + 4096;         // 4*128
    float* sb2  = sb1 + 512;          // 4*128
    float* sraw = sb2 + 512;          // 32*20
    int*   stype = (int*)(sraw + 640);

    int tid = threadIdx.x;
    int n0 = blockIdx.x * 32;

    for (int i = tid; i < NTYPE * INDIM * HID; i += 256) sW1[i] = W1[i];
    for (int i = tid; i < NTYPE * HID; i += 256) { sb1[i] = b1[i]; sb2[i] = b2[i]; }
    for (int i = tid; i < 32 * FEAT; i += 256) {
        int li = i / FEAT, k = i % FEAT;
        sraw[li * INDIM + k] = zemb[z[n0 + li] * FEAT + k];
    }
    if (tid < 32) {
        int node = n0 + tid;
        sraw[tid * INDIM + 16] = sd[node];
        sraw[tid * INDIM + 17] = dff[node];
        sraw[tid * INDIM + 18] = cond[node];
        sraw[tid * INDIM + 19] = mult[node];
        stype[tid] = ntype[node];
    }
    __syncthreads();

    // phase B: h1 = relu(raw @ W1[t] + b1[t])
    {
        int c = tid & 127, half = tid >> 7;
        for (int i = half; i < 32; i += 2) {
            int t = stype[i];
            float acc = sb1[t * HID + c];
            #pragma unroll
            for (int k = 0; k < INDIM; k++)
                acc += sraw[i * INDIM + k] * sW1[(t * INDIM + k) * HID + c];
            sh1[i * HID + c] = fmaxf(acc, 0.f);
        }
    }

    // phase C: x = h1 @ W2[t] + b2[t], one type pass at a time (W2 staged in smem)
    int lane = tid & 31, ig = tid >> 5, c0 = lane * 4;
    for (int t = 0; t < NTYPE; t++) {
        __syncthreads();
        const float4* W2t = (const float4*)(W2 + (size_t)t * HID * HID);
        for (int i = tid; i < HID * HID / 4; i += 256) ((float4*)sW2)[i] = W2t[i];
        __syncthreads();
        #pragma unroll
        for (int u = 0; u < 4; u++) {
            int i = ig * 4 + u;
            if (stype[i] != t) continue;
            float4 acc = *(const float4*)&sb2[t * HID + c0];
            const float* h1 = &sh1[i * HID];
            #pragma unroll 4
            for (int k = 0; k < HID; k++) {
                float xv = h1[k];
                float4 w = *(const float4*)&sW2[k * HID + c0];
                acc.x += xv * w.x; acc.y += xv * w.y;
                acc.z += xv * w.z; acc.w += xv * w.w;
            }
            *(float4*)&g_x[(size_t)(n0 + i) * HID + c0] = acc;
        }
    }
}

// ---------------- per-layer fused 4-matmul: y_r = x@rel_W[r] (r<3), xl = x@lin_W+lin_b ----------------
// block = 256 threads, 32-node tile; 4x4 register tiling per thread.
#define MM_SMEM_BYTES (81920)
__global__ __launch_bounds__(256, 2) void k_mm4(
    const float* __restrict__ relW, const float* __restrict__ linW,
    const float* __restrict__ linb)
{
    extern __shared__ __align__(16) float sm[];
    float* sx = sm;          // 32*128
    float* sW = sm + 4096;   // 128*128
    int tid = threadIdx.x;
    int n0 = blockIdx.x * 32;

    const float4* xsrc = (const float4*)(g_x + (size_t)n0 * HID);
    for (int i = tid; i < 4096 / 4; i += 256) ((float4*)sx)[i] = xsrc[i];

    int lane = tid & 31, ig = tid >> 5, c0 = lane * 4;
    const float* x0 = &sx[(ig * 4 + 0) * HID];
    const float* x1 = &sx[(ig * 4 + 1) * HID];
    const float* x2 = &sx[(ig * 4 + 2) * HID];
    const float* x3 = &sx[(ig * 4 + 3) * HID];

    #pragma unroll 1
    for (int m = 0; m < 4; m++) {
        const float* W = (m < 3) ? relW + (size_t)m * HID * HID : linW;
        __syncthreads();
        for (int i = tid; i < HID * HID / 4; i += 256)
            ((float4*)sW)[i] = ((const float4*)W)[i];
        __syncthreads();

        float4 acc0, acc1, acc2, acc3;
        if (m == 3) { acc0 = acc1 = acc2 = acc3 = *(const float4*)&linb[c0]; }
        else        { acc0 = acc1 = acc2 = acc3 = make_float4(0.f, 0.f, 0.f, 0.f); }

        #pragma unroll 8
        for (int k = 0; k < HID; k++) {
            float4 w = *(const float4*)&sW[k * HID + c0];
            float a0 = x0[k], a1 = x1[k], a2 = x2[k], a3 = x3[k];
            acc0.x += a0 * w.x; acc0.y += a0 * w.y; acc0.z += a0 * w.z; acc0.w += a0 * w.w;
            acc1.x += a1 * w.x; acc1.y += a1 * w.y; acc1.z += a1 * w.z; acc1.w += a1 * w.w;
            acc2.x += a2 * w.x; acc2.y += a2 * w.y; acc2.z += a2 * w.z; acc2.w += a2 * w.w;
            acc3.x += a3 * w.x; acc3.y += a3 * w.y; acc3.z += a3 * w.z; acc3.w += a3 * w.w;
        }
        float* out = (m < 3) ? g_y[m] : g_xl;
        *(float4*)&out[(size_t)(n0 + ig * 4 + 0) * HID + c0] = acc0;
        *(float4*)&out[(size_t)(n0 + ig * 4 + 1) * HID + c0] = acc1;
        *(float4*)&out[(size_t)(n0 + ig * 4 + 2) * HID + c0] = acc2;
        *(float4*)&out[(size_t)(n0 + ig * 4 + 3) * HID + c0] = acc3;
    }
}

// ---------------- edge gather + scatter-add (vector global reductions) ----------------
__device__ __forceinline__ void red_add_v4(float* addr, float4 v) {
    asm volatile("red.global.add.v4.f32 [%0], {%1, %2, %3, %4};"
                 :: "l"(addr), "f"(v.x), "f"(v.y), "f"(v.z), "f"(v.w) : "memory");
}

__global__ __launch_bounds__(256) void k_scatter(
    const int* __restrict__ src, const int* __restrict__ dst,
    const int* __restrict__ et)
{
    int w = (blockIdx.x * blockDim.x + threadIdx.x) >> 5;
    int lane = threadIdx.x & 31;
    int nw = (gridDim.x * blockDim.x) >> 5;
    for (int e = w; e < EE; e += nw) {
        int s = src[e], d = dst[e], r = et[e];
        float4 v = *(const float4*)&g_y[r][(size_t)s * HID + lane * 4];
        red_add_v4(&g_agg[(size_t)d * HID + lane * 4], v);
    }
}

// ---------------- finalize: h = xl + agg/deg, LayerNorm -> x ----------------
__global__ __launch_bounds__(256) void k_fin(const float* __restrict__ lng,
                                             const float* __restrict__ lnb)
{
    int node = (blockIdx.x * blockDim.x + threadIdx.x) >> 5;
    int lane = threadIdx.x & 31;
    float rdeg = 1.f / fmaxf((float)g_deg[node], 1.f);
    size_t base = (size_t)node * HID + lane * 4;
    float4 a  = *(const float4*)&g_agg[base];
    float4 xl = *(const float4*)&g_xl[base];
    float hx = xl.x + a.x * rdeg, hy = xl.y + a.y * rdeg;
    float hz = xl.z + a.z * rdeg, hw = xl.w + a.w * rdeg;
    float s = hx + hy + hz + hw;
    #pragma unroll
    for (int o = 16; o; o >>= 1) s += __shfl_xor_sync(0xffffffffu, s, o);
    float mu = s * (1.f / HID);
    float dx = hx - mu, dy = hy - mu, dz = hz - mu, dw = hw - mu;
    float v = dx * dx + dy * dy + dz * dz + dw * dw;
    #pragma unroll
    for (int o = 16; o; o >>= 1) v += __shfl_xor_sync(0xffffffffu, v, o);
    float rstd = rsqrtf(v * (1.f / HID) + LNEPS);
    float4 gg = *(const float4*)&lng[lane * 4];
    float4 bb = *(const float4*)&lnb[lane * 4];
    float4 o4 = make_float4(dx * rstd * gg.x + bb.x, dy * rstd * gg.y + bb.y,
                            dz * rstd * gg.z + bb.z, dw * rstd * gg.w + bb.w);
    *(float4*)&g_x[base] = o4;
}

// ---------------- pooling + regressor ----------------
__global__ __launch_bounds__(256) void k_pool() {
    __shared__ float4 spart[256];
    int lane = threadIdx.x & 31, w = threadIdx.x >> 5;
    float4 acc = make_float4(0.f, 0.f, 0.f, 0.f);
    for (int node = blockIdx.x * 8 + w; node < NN; node += gridDim.x * 8) {
        float4 v = *(const float4*)&g_x[(size_t)node * HID + lane * 4];
        acc.x += v.x; acc.y += v.y; acc.z += v.z; acc.w += v.w;
    }
    spart[threadIdx.x] = acc;
    __syncthreads();
    if (w == 0) {
        float4 s = spart[lane];
        #pragma unroll
        for (int q = 1; q < 8; q++) {
            float4 v = spart[q * 32 + lane];
            s.x += v.x; s.y += v.y; s.z += v.z; s.w += v.w;
        }
        atomicAdd(&g_pooled[lane * 4 + 0], s.x);
        atomicAdd(&g_pooled[lane * 4 + 1], s.y);
        atomicAdd(&g_pooled[lane * 4 + 2], s.z);
        atomicAdd(&g_pooled[lane * 4 + 3], s.w);
    }
}

__global__ void k_final(const float* __restrict__ regW,
                        const float* __restrict__ regb, float* __restrict__ out)
{
    int lane = threadIdx.x;
    float4 p = *(const float4*)&g_pooled[lane * 4];
    float4 w = *(const float4*)&regW[lane * 4];
    float s = p.x * w.x + p.y * w.y + p.z * w.z + p.w * w.w;
    #pragma unroll
    for (int o = 16; o; o >>= 1) s += __shfl_xor_sync(0xffffffffu, s, o);
    if (lane == 0) out[0] = s * (1.f / NN) + regb[0];
}

// ---------------- host launcher ----------------
extern "C" void kernel_launch(void* const* d_in, const int* in_sizes, int n_in,
                              void* d_out, int out_size)
{
    const int*   z    = (const int*)  d_in[0];
    const float* sd   = (const float*)d_in[1];
    const float* dff  = (const float*)d_in[2];
    const float* cond = (const float*)d_in[3];
    const float* mult = (const float*)d_in[4];
    const int*   nty  = (const int*)  d_in[5];
    const int*   ei   = (const int*)  d_in[6];
    const int*   et   = (const int*)  d_in[7];
    const float* zemb = (const float*)d_in[8];
    const float* eW1  = (const float*)d_in[9];
    const float* eb1  = (const float*)d_in[10];
    const float* eW2  = (const float*)d_in[11];
    const float* eb2  = (const float*)d_in[12];
    const float* linW = (const float*)d_in[13];
    const float* linb = (const float*)d_in[14];
    const float* relW = (const float*)d_in[15];
    const float* lng  = (const float*)d_in[16];
    const float* lnb  = (const float*)d_in[17];
    const float* regW = (const float*)d_in[18];
    const float* regb = (const float*)d_in[19];
    const int* src = ei, * dst = ei + EE;

    cudaFuncSetAttribute(k_enc, cudaFuncAttributeMaxDynamicSharedMemorySize, ENC_SMEM_BYTES);
    cudaFuncSetAttribute(k_mm4, cudaFuncAttributeMaxDynamicSharedMemorySize, MM_SMEM_BYTES);

    k_zero_misc<<<(NN + 255) / 256, 256>>>();
    k_deg<<<2048, 256>>>(dst);
    k_enc<<<NN / 32, 256, ENC_SMEM_BYTES>>>(z, sd, dff, cond, mult, nty, zemb,
                                            eW1, eb1, eW2, eb2);
    for (int l = 0; l < 2; l++) {
        k_mm4<<<NN / 32, 256, MM_SMEM_BYTES>>>(relW + (size_t)l * NREL * HID * HID,
                                               linW + (size_t)l * HID * HID,
                                               linb + (size_t)l * HID);
        k_zero_agg<<<2048, 256>>>();
        k_scatter<<<4096, 256>>>(src, dst, et);
        k_fin<<<NN / 8, 256>>>(lng + (size_t)l * HID, lnb + (size_t)l * HID);
    }
    k_pool<<<512, 256>>>();
    k_final<<<1, 32>>>(regW, regb, (float*)d_out);
}

// round 6
// speedup vs baseline: 1.7146x; 1.7146x over previous
#include <cuda_runtime.h>

#define NN 100000
#define NPAD 100096
#define EE 1600000
#define HID 128
#define FEAT 16
#define INDIM 20
#define NTYPE 4
#define NREL 3
#define LNEPS 1e-5f

// ---------------- scratch (static device globals; no allocation) ----------------
__device__ float g_x[(size_t)NPAD * HID];
__device__ float g_y[NREL][(size_t)NPAD * HID];
__device__ float g_xl[(size_t)NPAD * HID];
__device__ float g_agg[(size_t)NPAD * HID];
__device__ int   g_deg[NN];
__device__ float g_pooled[HID];

// ---------------- small utility kernels ----------------
__global__ void k_zero_misc() {
    int i = blockIdx.x * blockDim.x + threadIdx.x;
    if (i < NN) g_deg[i] = 0;
    if (i < HID) g_pooled[i] = 0.f;
}

__global__ void k_zero_agg() {
    size_t n = (size_t)NN * HID / 4;
    float4* p = (float4*)g_agg;
    size_t st = (size_t)gridDim.x * blockDim.x;
    for (size_t i = (size_t)blockIdx.x * blockDim.x + threadIdx.x; i < n; i += st)
        p[i] = make_float4(0.f, 0.f, 0.f, 0.f);
}

__global__ void k_deg(const int* __restrict__ dst) {
    int st = gridDim.x * blockDim.x;
    for (int i = blockIdx.x * blockDim.x + threadIdx.x; i < EE; i += st)
        atomicAdd(&g_deg[dst[i]], 1);
}

// ---------------- f32x2 helpers ----------------
__device__ __forceinline__ void ffma2(unsigned long long& d, unsigned long long a,
                                      unsigned long long b) {
    asm("fma.rn.f32x2 %0, %1, %2, %3;" : "=l"(d) : "l"(a), "l"(b), "l"(d));
}
__device__ __forceinline__ float pairsum(unsigned long long v) {
    float2 f = *reinterpret_cast<float2*>(&v);
    return f.x + f.y;
}
__device__ __forceinline__ unsigned long long packlo(float v) {
    return (unsigned long long)__float_as_uint(v);  // lo = v, hi = 0
}

// ---------------- encoder: per-type 2-layer MLP ----------------
#define ENC_SMEM_BYTES (129664)
__global__ __launch_bounds__(256) void k_enc(
    const int* __restrict__ z, const float* __restrict__ sd,
    const float* __restrict__ dff, const float* __restrict__ cond,
    const float* __restrict__ mult, const int* __restrict__ ntype,
    const float* __restrict__ zemb,
    const float* __restrict__ W1, const float* __restrict__ b1,
    const float* __restrict__ W2, const float* __restrict__ b2)
{
    extern __shared__ __align__(16) float sm[];
    float* sW2  = sm;                 // 128*128
    float* sW1  = sm + 16384;         // 4*20*128
    float* sh1  = sW1 + 10240;        // 32*128
    float* sb1  = sh1 + 4096;         // 4*128
    float* sb2  = sb1 + 512;          // 4*128
    float* sraw = sb2 + 512;          // 32*20
    int*   stype = (int*)(sraw + 640);

    int tid = threadIdx.x;
    int n0 = blockIdx.x * 32;

    for (int i = tid; i < NTYPE * INDIM * HID; i += 256) sW1[i] = W1[i];
    for (int i = tid; i < NTYPE * HID; i += 256) { sb1[i] = b1[i]; sb2[i] = b2[i]; }
    for (int i = tid; i < 32 * FEAT; i += 256) {
        int li = i / FEAT, k = i % FEAT;
        sraw[li * INDIM + k] = zemb[z[n0 + li] * FEAT + k];
    }
    if (tid < 32) {
        int node = n0 + tid;
        sraw[tid * INDIM + 16] = sd[node];
        sraw[tid * INDIM + 17] = dff[node];
        sraw[tid * INDIM + 18] = cond[node];
        sraw[tid * INDIM + 19] = mult[node];
        stype[tid] = ntype[node];
    }
    __syncthreads();

    // phase B: h1 = relu(raw @ W1[t] + b1[t])
    {
        int c = tid & 127, half = tid >> 7;
        for (int i = half; i < 32; i += 2) {
            int t = stype[i];
            float acc = sb1[t * HID + c];
            #pragma unroll
            for (int k = 0; k < INDIM; k++)
                acc += sraw[i * INDIM + k] * sW1[(t * INDIM + k) * HID + c];
            sh1[i * HID + c] = fmaxf(acc, 0.f);
        }
    }

    // phase C: x = h1 @ W2[t] + b2[t]
    int lane = tid & 31, ig = tid >> 5, c0 = lane * 4;
    for (int t = 0; t < NTYPE; t++) {
        __syncthreads();
        const float4* W2t = (const float4*)(W2 + (size_t)t * HID * HID);
        for (int i = tid; i < HID * HID / 4; i += 256) ((float4*)sW2)[i] = W2t[i];
        __syncthreads();
        #pragma unroll
        for (int u = 0; u < 4; u++) {
            int i = ig * 4 + u;
            if (stype[i] != t) continue;
            float4 acc = *(const float4*)&sb2[t * HID + c0];
            const float* h1 = &sh1[i * HID];
            #pragma unroll 4
            for (int k = 0; k < HID; k++) {
                float xv = h1[k];
                float4 w = *(const float4*)&sW2[k * HID + c0];
                acc.x += xv * w.x; acc.y += xv * w.y;
                acc.z += xv * w.z; acc.w += xv * w.w;
            }
            *(float4*)&g_x[(size_t)(n0 + i) * HID + c0] = acc;
        }
    }
}

// ---------------- per-layer fused 4-matmul (f32x2, 64-node tiles) ----------------
// y_r = x @ rel_W[r] (r<3), xl = x @ lin_W + lin_b
// Block: 256 threads, 64 nodes. Warp w owns nodes w*8..w*8+7; lane owns cols lane*4..+3.
// Accumulators are f32x2 packed over (even-k, odd-k) partial sums; reduced at the end.
// Weights staged in smem as k-pair-interleaved float2 with a column permutation so
// that both per-warp weight loads are contiguous 512B LDS.128s (conflict-free):
//   slot(kp, c) = kp*128 + ((c&2) ? 64 : 0) + (c>>2)*2 + (c&1);  value = (W[2kp][c], W[2kp+1][c])
#define MM_SMEM_BYTES (98304)
__global__ __launch_bounds__(256, 2) void k_mm4(
    const float* __restrict__ relW, const float* __restrict__ linW,
    const float* __restrict__ linb)
{
    extern __shared__ __align__(16) float sm[];
    float*  sx  = sm;                          // 64 x 128 floats (32KB)
    float2* sw2 = (float2*)(sm + 64 * HID);    // 64 kp x 128 slots (64KB)

    int tid = threadIdx.x;
    int lane = tid & 31, w = tid >> 5;
    int n0 = blockIdx.x * 64;
    int c0 = lane * 4;
    int nodebase = w * 8;

    // stage x (coalesced; g_x padded to NPAD so tail block is in-bounds)
    {
        const float4* src = (const float4*)(g_x + (size_t)n0 * HID);
        float4* dst4 = (float4*)sx;
        for (int i = tid; i < 64 * 32; i += 256) dst4[i] = src[i];
    }

    for (int m = 0; m < 4; m++) {
        const float* W = (m < 3) ? relW + (size_t)m * HID * HID : linW;
        __syncthreads();   // protect sw2 from readers of previous m
        // stage weights: thread handles (kp, colgroup-of-4)
        for (int i = tid; i < 64 * 32; i += 256) {
            int kp = i >> 5, cg = i & 31;
            float4 a = *(const float4*)&W[(2 * kp) * HID + cg * 4];
            float4 b = *(const float4*)&W[(2 * kp + 1) * HID + cg * 4];
            float2* base = &sw2[kp * 128];
            *(float4*)&base[cg * 2]      = make_float4(a.x, b.x, a.y, b.y); // cols 4cg, 4cg+1
            *(float4*)&base[64 + cg * 2] = make_float4(a.z, b.z, a.w, b.w); // cols 4cg+2, 4cg+3
        }
        __syncthreads();

        unsigned long long acc[8][4];
        if (m == 3) {
            unsigned long long b0 = packlo(linb[c0 + 0]), b1 = packlo(linb[c0 + 1]);
            unsigned long long b2 = packlo(linb[c0 + 2]), b3 = packlo(linb[c0 + 3]);
            #pragma unroll
            for (int n = 0; n < 8; n++) {
                acc[n][0] = b0; acc[n][1] = b1; acc[n][2] = b2; acc[n][3] = b3;
            }
        } else {
            #pragma unroll
            for (int n = 0; n < 8; n++)
                acc[n][0] = acc[n][1] = acc[n][2] = acc[n][3] = 0ull;
        }

        #pragma unroll 4
        for (int c4 = 0; c4 < 32; c4++) {       // k-chunk of 4 = kpairs (2c4, 2c4+1)
            const float2* rA = &sw2[(2 * c4) * 128];
            const float2* rB = &sw2[(2 * c4 + 1) * 128];
            ulonglong2 a0 = *(const ulonglong2*)&rA[lane * 2];       // cols c0, c0+1
            ulonglong2 a1 = *(const ulonglong2*)&rA[64 + lane * 2];  // cols c0+2, c0+3
            ulonglong2 b0 = *(const ulonglong2*)&rB[lane * 2];
            ulonglong2 b1 = *(const ulonglong2*)&rB[64 + lane * 2];
            #pragma unroll
            for (int n = 0; n < 8; n++) {
                ulonglong2 xq = *(const ulonglong2*)&sx[(nodebase + n) * HID + c4 * 4];
                ffma2(acc[n][0], xq.x, a0.x);
                ffma2(acc[n][1], xq.x, a0.y);
                ffma2(acc[n][2], xq.x, a1.x);
                ffma2(acc[n][3], xq.x, a1.y);
                ffma2(acc[n][0], xq.y, b0.x);
                ffma2(acc[n][1], xq.y, b0.y);
                ffma2(acc[n][2], xq.y, b1.x);
                ffma2(acc[n][3], xq.y, b1.y);
            }
        }

        float* out = (m < 3) ? g_y[m] : g_xl;
        #pragma unroll
        for (int n = 0; n < 8; n++) {
            int ng = n0 + nodebase + n;
            if (ng < NN) {
                float4 o = make_float4(pairsum(acc[n][0]), pairsum(acc[n][1]),
                                       pairsum(acc[n][2]), pairsum(acc[n][3]));
                *(float4*)&out[(size_t)ng * HID + c0] = o;
            }
        }
    }
}

// ---------------- edge gather + scatter-add (vector global reductions) ----------------
__device__ __forceinline__ void red_add_v4(float* addr, float4 v) {
    asm volatile("red.global.add.v4.f32 [%0], {%1, %2, %3, %4};"
                 :: "l"(addr), "f"(v.x), "f"(v.y), "f"(v.z), "f"(v.w) : "memory");
}

__global__ __launch_bounds__(256) void k_scatter(
    const int* __restrict__ src, const int* __restrict__ dst,
    const int* __restrict__ et)
{
    int w = (blockIdx.x * blockDim.x + threadIdx.x) >> 5;
    int lane = threadIdx.x & 31;
    int nw = (gridDim.x * blockDim.x) >> 5;
    for (int e = w; e < EE; e += nw) {
        int s = src[e], d = dst[e], r = et[e];
        float4 v = *(const float4*)&g_y[r][(size_t)s * HID + lane * 4];
        red_add_v4(&g_agg[(size_t)d * HID + lane * 4], v);
    }
}

// ---------------- finalize: h = xl + agg/deg, LayerNorm -> x ----------------
__global__ __launch_bounds__(256) void k_fin(const float* __restrict__ lng,
                                             const float* __restrict__ lnb)
{
    int node = (blockIdx.x * blockDim.x + threadIdx.x) >> 5;
    int lane = threadIdx.x & 31;
    float rdeg = 1.f / fmaxf((float)g_deg[node], 1.f);
    size_t base = (size_t)node * HID + lane * 4;
    float4 a  = *(const float4*)&g_agg[base];
    float4 xl = *(const float4*)&g_xl[base];
    float hx = xl.x + a.x * rdeg, hy = xl.y + a.y * rdeg;
    float hz = xl.z + a.z * rdeg, hw = xl.w + a.w * rdeg;
    float s = hx + hy + hz + hw;
    #pragma unroll
    for (int o = 16; o; o >>= 1) s += __shfl_xor_sync(0xffffffffu, s, o);
    float mu = s * (1.f / HID);
    float dx = hx - mu, dy = hy - mu, dz = hz - mu, dw = hw - mu;
    float v = dx * dx + dy * dy + dz * dz + dw * dw;
    #pragma unroll
    for (int o = 16; o; o >>= 1) v += __shfl_xor_sync(0xffffffffu, v, o);
    float rstd = rsqrtf(v * (1.f / HID) + LNEPS);
    float4 gg = *(const float4*)&lng[lane * 4];
    float4 bb = *(const float4*)&lnb[lane * 4];
    float4 o4 = make_float4(dx * rstd * gg.x + bb.x, dy * rstd * gg.y + bb.y,
                            dz * rstd * gg.z + bb.z, dw * rstd * gg.w + bb.w);
    *(float4*)&g_x[base] = o4;
}

// ---------------- pooling + regressor ----------------
__global__ __launch_bounds__(256) void k_pool() {
    __shared__ float4 spart[256];
    int lane = threadIdx.x & 31, w = threadIdx.x >> 5;
    float4 acc = make_float4(0.f, 0.f, 0.f, 0.f);
    for (int node = blockIdx.x * 8 + w; node < NN; node += gridDim.x * 8) {
        float4 v = *(const float4*)&g_x[(size_t)node * HID + lane * 4];
        acc.x += v.x; acc.y += v.y; acc.z += v.z; acc.w += v.w;
    }
    spart[threadIdx.x] = acc;
    __syncthreads();
    if (w == 0) {
        float4 s = spart[lane];
        #pragma unroll
        for (int q = 1; q < 8; q++) {
            float4 v = spart[q * 32 + lane];
            s.x += v.x; s.y += v.y; s.z += v.z; s.w += v.w;
        }
        atomicAdd(&g_pooled[lane * 4 + 0], s.x);
        atomicAdd(&g_pooled[lane * 4 + 1], s.y);
        atomicAdd(&g_pooled[lane * 4 + 2], s.z);
        atomicAdd(&g_pooled[lane * 4 + 3], s.w);
    }
}

__global__ void k_final(const float* __restrict__ regW,
                        const float* __restrict__ regb, float* __restrict__ out)
{
    int lane = threadIdx.x;
    float4 p = *(const float4*)&g_pooled[lane * 4];
    float4 w = *(const float4*)&regW[lane * 4];
    float s = p.x * w.x + p.y * w.y + p.z * w.z + p.w * w.w;
    #pragma unroll
    for (int o = 16; o; o >>= 1) s += __shfl_xor_sync(0xffffffffu, s, o);
    if (lane == 0) out[0] = s * (1.f / NN) + regb[0];
}

// ---------------- host launcher ----------------
extern "C" void kernel_launch(void* const* d_in, const int* in_sizes, int n_in,
                              void* d_out, int out_size)
{
    const int*   z    = (const int*)  d_in[0];
    const float* sd   = (const float*)d_in[1];
    const float* dff  = (const float*)d_in[2];
    const float* cond = (const float*)d_in[3];
    const float* mult = (const float*)d_in[4];
    const int*   nty  = (const int*)  d_in[5];
    const int*   ei   = (const int*)  d_in[6];
    const int*   et   = (const int*)  d_in[7];
    const float* zemb = (const float*)d_in[8];
    const float* eW1  = (const float*)d_in[9];
    const float* eb1  = (const float*)d_in[10];
    const float* eW2  = (const float*)d_in[11];
    const float* eb2  = (const float*)d_in[12];
    const float* linW = (const float*)d_in[13];
    const float* linb = (const float*)d_in[14];
    const float* relW = (const float*)d_in[15];
    const float* lng  = (const float*)d_in[16];
    const float* lnb  = (const float*)d_in[17];
    const float* regW = (const float*)d_in[18];
    const float* regb = (const float*)d_in[19];
    const int* src = ei, * dst = ei + EE;

    cudaFuncSetAttribute(k_enc, cudaFuncAttributeMaxDynamicSharedMemorySize, ENC_SMEM_BYTES);
    cudaFuncSetAttribute(k_mm4, cudaFuncAttributeMaxDynamicSharedMemorySize, MM_SMEM_BYTES);

    k_zero_misc<<<(NN + 255) / 256, 256>>>();
    k_deg<<<2048, 256>>>(dst);
    k_enc<<<NN / 32, 256, ENC_SMEM_BYTES>>>(z, sd, dff, cond, mult, nty, zemb,
                                            eW1, eb1, eW2, eb2);
    int mmblocks = (NN + 63) / 64;
    for (int l = 0; l < 2; l++) {
        k_mm4<<<mmblocks, 256, MM_SMEM_BYTES>>>(relW + (size_t)l * NREL * HID * HID,
                                                linW + (size_t)l * HID * HID,
                                                linb + (size_t)l * HID);
        k_zero_agg<<<2048, 256>>>();
        k_scatter<<<4096, 256>>>(src, dst, et);
        k_fin<<<NN / 8, 256>>>(lng + (size_t)l * HID, lnb + (size_t)l * HID);
    }
    k_pool<<<512, 256>>>();
    k_final<<<1, 32>>>(regW, regb, (float*)d_out);
}

// round 8
// speedup vs baseline: 2.1827x; 1.2730x over previous
#include <cuda_runtime.h>

#define NN 100000
#define NPAD 100096
#define EE 1600000
#define HID 128
#define FEAT 16
#define INDIM 20
#define NTYPE 4
#define NREL 3
#define LNEPS 1e-5f
#define NB_SCAN 98   // 98 * 1024 >= NN+1

// ---------------- scratch (static device globals; no allocation) ----------------
__device__ float g_x[(size_t)NPAD * HID];
__device__ float g_y[NREL][(size_t)NPAD * HID];   // per-relation degree-normalized sums
__device__ int   g_deg[NN];
__device__ int   g_off[NN + 1];
__device__ int   g_cur[NN];
__device__ int   g_bsum[NB_SCAN];
__device__ unsigned g_eidx[EE];
__device__ unsigned g_torder[NN];
__device__ int   g_tcnt[NTYPE];
__device__ int   g_tcur[NTYPE];
__device__ float g_pooled[HID];

// ---------------- f32x2 helpers ----------------
__device__ __forceinline__ void ffma2(unsigned long long& d, unsigned long long a,
                                      unsigned long long b) {
    asm("fma.rn.f32x2 %0, %1, %2, %3;" : "=l"(d) : "l"(a), "l"(b), "l"(d));
}
__device__ __forceinline__ float pairsum(unsigned long long v) {
    float2 f = *reinterpret_cast<float2*>(&v);
    return f.x + f.y;
}
__device__ __forceinline__ unsigned long long packlo(float v) {
    return (unsigned long long)__float_as_uint(v);
}

// ---------------- setup kernels ----------------
__global__ void k_zero_misc() {
    int i = blockIdx.x * blockDim.x + threadIdx.x;
    if (i < NN) g_deg[i] = 0;
    if (i < HID) g_pooled[i] = 0.f;
    if (i < NTYPE) g_tcnt[i] = 0;
}

__global__ void k_deg(const int* __restrict__ dst) {
    int i = blockIdx.x * blockDim.x + threadIdx.x;
    if (i < EE) atomicAdd(&g_deg[dst[i]], 1);
}

__global__ void k_count(const int* __restrict__ nty) {
    int i = blockIdx.x * blockDim.x + threadIdx.x;
    if (i < NN) atomicAdd(&g_tcnt[nty[i]], 1);
}

__global__ void k_toff() {
    if (threadIdx.x == 0) {
        int s = 0;
        for (int t = 0; t < NTYPE; t++) { g_tcur[t] = s; s += g_tcnt[t]; }
    }
}

__global__ void k_tfill(const int* __restrict__ nty) {
    int i = blockIdx.x * blockDim.x + threadIdx.x;
    if (i < NN) {
        int t = nty[i];
        int pos = atomicAdd(&g_tcur[t], 1);
        g_torder[pos] = (unsigned)i | ((unsigned)t << 20);
    }
}

// ---------------- CSR scan (offsets from degrees) ----------------
__global__ __launch_bounds__(1024) void k_scan1() {
    __shared__ int s[1024];
    int b = blockIdx.x, tid = threadIdx.x;
    int i = b * 1024 + tid;
    int v = (i < NN) ? g_deg[i] : 0;
    s[tid] = v;
    __syncthreads();
    for (int off = 1; off < 1024; off <<= 1) {
        int t = (tid >= off) ? s[tid - off] : 0;
        __syncthreads();
        s[tid] += t;
        __syncthreads();
    }
    if (i < NN) g_off[i] = s[tid] - v;          // local exclusive
    if (tid == 1023) g_bsum[b] = s[1023];
}

__global__ void k_scan2() {
    if (threadIdx.x == 0) {
        int s = 0;
        for (int b = 0; b < NB_SCAN; b++) { int v = g_bsum[b]; g_bsum[b] = s; s += v; }
    }
}

__global__ __launch_bounds__(1024) void k_scan3() {
    int b = blockIdx.x, i = b * 1024 + threadIdx.x;
    if (i < NN) {
        int val = g_off[i] + g_bsum[b];
        g_off[i] = val;
        g_cur[i] = val;
    }
    if (i == NN) g_off[NN] = EE;
}

__global__ void k_fill(const int* __restrict__ src, const int* __restrict__ dst,
                       const int* __restrict__ et) {
    int e = blockIdx.x * blockDim.x + threadIdx.x;
    if (e < EE) {
        int d = dst[e];
        int pos = atomicAdd(&g_cur[d], 1);
        g_eidx[pos] = (unsigned)src[e] | ((unsigned)et[e] << 17);
    }
}

// ---------------- encoder: per-type 2-layer MLP (type-bucketed) ----------------
#define ENC_SMEM_BYTES (129920)
__global__ __launch_bounds__(256) void k_enc(
    const int* __restrict__ z, const float* __restrict__ sd,
    const float* __restrict__ dff, const float* __restrict__ cond,
    const float* __restrict__ mult,
    const float* __restrict__ zemb,
    const float* __restrict__ W1, const float* __restrict__ b1,
    const float* __restrict__ W2, const float* __restrict__ b2)
{
    extern __shared__ __align__(16) float sm[];
    float* sW2  = sm;                 // 128*128
    float* sW1  = sm + 16384;         // 4*20*128
    float* sh1  = sW1 + 10240;        // 32*128
    float* sb1  = sh1 + 4096;         // 4*128
    float* sb2  = sb1 + 512;          // 4*128
    float* sraw = sb2 + 512;          // 32*20
    int*   stype = (int*)(sraw + 640);
    int*   snode = stype + 32;
    int*   sz    = snode + 32;

    int tid = threadIdx.x;
    int n0 = blockIdx.x * 32;

    if (tid < 32) {
        unsigned v = g_torder[n0 + tid];
        int node = v & 0xFFFFF;
        snode[tid] = node;
        stype[tid] = v >> 20;
        sz[tid]    = z[node];
        sraw[tid * INDIM + 16] = sd[node];
        sraw[tid * INDIM + 17] = dff[node];
        sraw[tid * INDIM + 18] = cond[node];
        sraw[tid * INDIM + 19] = mult[node];
    }
    for (int i = tid; i < NTYPE * INDIM * HID; i += 256) sW1[i] = W1[i];
    for (int i = tid; i < NTYPE * HID; i += 256) { sb1[i] = b1[i]; sb2[i] = b2[i]; }
    __syncthreads();
    for (int i = tid; i < 32 * FEAT; i += 256) {
        int li = i / FEAT, k = i % FEAT;
        sraw[li * INDIM + k] = zemb[sz[li] * FEAT + k];   // <-- z-embedding via z[node]
    }
    __syncthreads();

    // phase B: h1 = relu(raw @ W1[t] + b1[t])
    {
        int c = tid & 127, half = tid >> 7;
        for (int i = half; i < 32; i += 2) {
            int t = stype[i];
            float acc = sb1[t * HID + c];
            #pragma unroll
            for (int k = 0; k < INDIM; k++)
                acc += sraw[i * INDIM + k] * sW1[(t * INDIM + k) * HID + c];
            sh1[i * HID + c] = fmaxf(acc, 0.f);
        }
    }

    // phase C: x = h1 @ W2[t] + b2[t]. torder is sorted by type, so each block
    // spans a contiguous type range -> W2 staged 1-2 times.
    int lane = tid & 31, ig = tid >> 5, c0 = lane * 4;
    int tmin = stype[0], tmax = stype[31];
    for (int t = tmin; t <= tmax; t++) {
        __syncthreads();
        const float4* W2t = (const float4*)(W2 + (size_t)t * HID * HID);
        for (int i = tid; i < HID * HID / 4; i += 256) ((float4*)sW2)[i] = W2t[i];
        __syncthreads();
        #pragma unroll
        for (int u = 0; u < 4; u++) {
            int i = ig * 4 + u;
            if (stype[i] != t) continue;
            float4 acc = *(const float4*)&sb2[t * HID + c0];
            const float* h1 = &sh1[i * HID];
            #pragma unroll 4
            for (int k = 0; k < HID; k++) {
                float xv = h1[k];
                float4 w = *(const float4*)&sW2[k * HID + c0];
                acc.x += xv * w.x; acc.y += xv * w.y;
                acc.z += xv * w.z; acc.w += xv * w.w;
            }
            *(float4*)&g_x[(size_t)snode[i] * HID + c0] = acc;
        }
    }
}

// ---------------- gather: per-node, per-relation sums of x[src] (CSR, no atomics) ----------------
__global__ __launch_bounds__(256) void k_gather() {
    int wid = threadIdx.x >> 5, lane = threadIdx.x & 31;
    int node = blockIdx.x * 8 + wid;                    // NN % 8 == 0
    int rs = g_off[node], re = g_off[node + 1];
    float4 a0 = make_float4(0.f, 0.f, 0.f, 0.f);
    float4 a1 = a0, a2 = a0;
    for (int base = rs; base < re; base += 32) {
        int n = min(32, re - base);
        unsigned ep = (base + lane < re) ? g_eidx[base + lane] : 0u;
        for (int j = 0; j < n; j++) {
            unsigned v = __shfl_sync(0xffffffffu, ep, j);
            int s = v & 0x1FFFF;
            int r = v >> 17;
            float4 xv = *(const float4*)&g_x[(size_t)s * HID + lane * 4];
            if (r == 0)      { a0.x += xv.x; a0.y += xv.y; a0.z += xv.z; a0.w += xv.w; }
            else if (r == 1) { a1.x += xv.x; a1.y += xv.y; a1.z += xv.z; a1.w += xv.w; }
            else             { a2.x += xv.x; a2.y += xv.y; a2.z += xv.z; a2.w += xv.w; }
        }
    }
    float inv = 1.f / (float)max(re - rs, 1);
    size_t o = (size_t)node * HID + lane * 4;
    *(float4*)&g_y[0][o] = make_float4(a0.x * inv, a0.y * inv, a0.z * inv, a0.w * inv);
    *(float4*)&g_y[1][o] = make_float4(a1.x * inv, a1.y * inv, a1.z * inv, a1.w * inv);
    *(float4*)&g_y[2][o] = make_float4(a2.x * inv, a2.y * inv, a2.z * inv, a2.w * inv);
}

// ---------------- fused 4-GEMM + LayerNorm ----------------
// h = xsum0@W0 + xsum1@W1 + xsum2@W2 + x@linW + linb ; x = LN(h)*g + b
#define MM_SMEM_BYTES (98304)
__global__ __launch_bounds__(256, 2) void k_mm5(
    const float* __restrict__ relW, const float* __restrict__ linW,
    const float* __restrict__ linb, const float* __restrict__ lng,
    const float* __restrict__ lnb)
{
    extern __shared__ __align__(16) float sm[];
    float*  sx  = sm;                          // 64 x 128 floats (32KB)
    float2* sw2 = (float2*)(sm + 64 * HID);    // 64 kp x 128 slots (64KB)

    int tid = threadIdx.x;
    int lane = tid & 31, w = tid >> 5;
    int n0 = blockIdx.x * 64;
    int c0 = lane * 4;
    int nodebase = w * 8;

    unsigned long long acc[8][4];
    {
        unsigned long long b0 = packlo(linb[c0 + 0]), b1 = packlo(linb[c0 + 1]);
        unsigned long long b2 = packlo(linb[c0 + 2]), b3 = packlo(linb[c0 + 3]);
        #pragma unroll
        for (int n = 0; n < 8; n++) {
            acc[n][0] = b0; acc[n][1] = b1; acc[n][2] = b2; acc[n][3] = b3;
        }
    }

    #pragma unroll 1
    for (int m = 0; m < 4; m++) {
        const float* W   = (m < 3) ? relW + (size_t)m * HID * HID : linW;
        const float* inp = (m < 3) ? g_y[m] : g_x;
        __syncthreads();
        // stage input tile
        {
            const float4* src = (const float4*)(inp + (size_t)n0 * HID);
            float4* dst4 = (float4*)sx;
            for (int i = tid; i < 64 * 32; i += 256) dst4[i] = src[i];
        }
        // stage weights (k-pair interleaved, column-permuted; conflict-free LDS.128)
        for (int i = tid; i < 64 * 32; i += 256) {
            int kp = i >> 5, cg = i & 31;
            float4 a = *(const float4*)&W[(2 * kp) * HID + cg * 4];
            float4 b = *(const float4*)&W[(2 * kp + 1) * HID + cg * 4];
            float2* base = &sw2[kp * 128];
            *(float4*)&base[cg * 2]      = make_float4(a.x, b.x, a.y, b.y);
            *(float4*)&base[64 + cg * 2] = make_float4(a.z, b.z, a.w, b.w);
        }
        __syncthreads();

        #pragma unroll 4
        for (int c4 = 0; c4 < 32; c4++) {
            const float2* rA = &sw2[(2 * c4) * 128];
            const float2* rB = &sw2[(2 * c4 + 1) * 128];
            ulonglong2 a0 = *(const ulonglong2*)&rA[lane * 2];
            ulonglong2 a1 = *(const ulonglong2*)&rA[64 + lane * 2];
            ulonglong2 b0 = *(const ulonglong2*)&rB[lane * 2];
            ulonglong2 b1 = *(const ulonglong2*)&rB[64 + lane * 2];
            #pragma unroll
            for (int n = 0; n < 8; n++) {
                ulonglong2 xq = *(const ulonglong2*)&sx[(nodebase + n) * HID + c4 * 4];
                ffma2(acc[n][0], xq.x, a0.x);
                ffma2(acc[n][1], xq.x, a0.y);
                ffma2(acc[n][2], xq.x, a1.x);
                ffma2(acc[n][3], xq.x, a1.y);
                ffma2(acc[n][0], xq.y, b0.x);
                ffma2(acc[n][1], xq.y, b0.y);
                ffma2(acc[n][2], xq.y, b1.x);
                ffma2(acc[n][3], xq.y, b1.y);
            }
        }
    }

    // fused LayerNorm + write back to g_x
    float4 gg = *(const float4*)&lng[c0];
    float4 bb = *(const float4*)&lnb[c0];
    #pragma unroll
    for (int n = 0; n < 8; n++) {
        int ng = n0 + nodebase + n;
        float hx = pairsum(acc[n][0]), hy = pairsum(acc[n][1]);
        float hz = pairsum(acc[n][2]), hw = pairsum(acc[n][3]);
        float s = hx + hy + hz + hw;
        #pragma unroll
        for (int o = 16; o; o >>= 1) s += __shfl_xor_sync(0xffffffffu, s, o);
        float mu = s * (1.f / HID);
        float dx = hx - mu, dy = hy - mu, dz = hz - mu, dw = hw - mu;
        float v = dx * dx + dy * dy + dz * dz + dw * dw;
        #pragma unroll
        for (int o = 16; o; o >>= 1) v += __shfl_xor_sync(0xffffffffu, v, o);
        float rstd = rsqrtf(v * (1.f / HID) + LNEPS);
        if (ng < NN) {
            float4 o4 = make_float4(dx * rstd * gg.x + bb.x, dy * rstd * gg.y + bb.y,
                                    dz * rstd * gg.z + bb.z, dw * rstd * gg.w + bb.w);
            *(float4*)&g_x[(size_t)ng * HID + c0] = o4;
        }
    }
}

// ---------------- pooling + regressor ----------------
__global__ __launch_bounds__(256) void k_pool() {
    __shared__ float4 spart[256];
    int lane = threadIdx.x & 31, w = threadIdx.x >> 5;
    float4 acc = make_float4(0.f, 0.f, 0.f, 0.f);
    for (int node = blockIdx.x * 8 + w; node < NN; node += gridDim.x * 8) {
        float4 v = *(const float4*)&g_x[(size_t)node * HID + lane * 4];
        acc.x += v.x; acc.y += v.y; acc.z += v.z; acc.w += v.w;
    }
    spart[threadIdx.x] = acc;
    __syncthreads();
    if (w == 0) {
        float4 s = spart[lane];
        #pragma unroll
        for (int q = 1; q < 8; q++) {
            float4 v = spart[q * 32 + lane];
            s.x += v.x; s.y += v.y; s.z += v.z; s.w += v.w;
        }
        atomicAdd(&g_pooled[lane * 4 + 0], s.x);
        atomicAdd(&g_pooled[lane * 4 + 1], s.y);
        atomicAdd(&g_pooled[lane * 4 + 2], s.z);
        atomicAdd(&g_pooled[lane * 4 + 3], s.w);
    }
}

__global__ void k_final(const float* __restrict__ regW,
                        const float* __restrict__ regb, float* __restrict__ out)
{
    int lane = threadIdx.x;
    float4 p = *(const float4*)&g_pooled[lane * 4];
    float4 w = *(const float4*)&regW[lane * 4];
    float s = p.x * w.x + p.y * w.y + p.z * w.z + p.w * w.w;
    #pragma unroll
    for (int o = 16; o; o >>= 1) s += __shfl_xor_sync(0xffffffffu, s, o);
    if (lane == 0) out[0] = s * (1.f / NN) + regb[0];
}

// ---------------- host launcher ----------------
extern "C" void kernel_launch(void* const* d_in, const int* in_sizes, int n_in,
                              void* d_out, int out_size)
{
    const int*   z    = (const int*)  d_in[0];
    const float* sd   = (const float*)d_in[1];
    const float* dff  = (const float*)d_in[2];
    const float* cond = (const float*)d_in[3];
    const float* mult = (const float*)d_in[4];
    const int*   nty  = (const int*)  d_in[5];
    const int*   ei   = (const int*)  d_in[6];
    const int*   et   = (const int*)  d_in[7];
    const float* zemb = (const float*)d_in[8];
    const float* eW1  = (const float*)d_in[9];
    const float* eb1  = (const float*)d_in[10];
    const float* eW2  = (const float*)d_in[11];
    const float* eb2  = (const float*)d_in[12];
    const float* linW = (const float*)d_in[13];
    const float* linb = (const float*)d_in[14];
    const float* relW = (const float*)d_in[15];
    const float* lng  = (const float*)d_in[16];
    const float* lnb  = (const float*)d_in[17];
    const float* regW = (const float*)d_in[18];
    const float* regb = (const float*)d_in[19];
    const int* src = ei, * dst = ei + EE;

    cudaFuncSetAttribute(k_enc, cudaFuncAttributeMaxDynamicSharedMemorySize, ENC_SMEM_BYTES);
    cudaFuncSetAttribute(k_mm5, cudaFuncAttributeMaxDynamicSharedMemorySize, MM_SMEM_BYTES);

    // setup: degree histogram, type buckets, CSR
    k_zero_misc<<<(NN + 255) / 256, 256>>>();
    k_deg<<<(EE + 255) / 256, 256>>>(dst);
    k_count<<<(NN + 255) / 256, 256>>>(nty);
    k_toff<<<1, 32>>>();
    k_tfill<<<(NN + 255) / 256, 256>>>(nty);
    k_scan1<<<NB_SCAN, 1024>>>();
    k_scan2<<<1, 32>>>();
    k_scan3<<<NB_SCAN, 1024>>>();
    k_fill<<<(EE + 255) / 256, 256>>>(src, dst, et);

    // encoder
    k_enc<<<NN / 32, 256, ENC_SMEM_BYTES>>>(z, sd, dff, cond, mult, zemb,
                                            eW1, eb1, eW2, eb2);
    // GNN layers
    int mmblocks = (NN + 63) / 64;
    for (int l = 0; l < 2; l++) {
        k_gather<<<NN / 8, 256>>>();
        k_mm5<<<mmblocks, 256, MM_SMEM_BYTES>>>(relW + (size_t)l * NREL * HID * HID,
                                                linW + (size_t)l * HID * HID,
                                                linb + (size_t)l * HID,
                                                lng + (size_t)l * HID,
                                                lnb + (size_t)l * HID);
    }
    k_pool<<<512, 256>>>();
    k_final<<<1, 32>>>(regW, regb, (float*)d_out);
}

// round 11
// speedup vs baseline: 2.4770x; 1.1348x over previous
#include <cuda_runtime.h>
#include <cuda_bf16.h>

#define NN 100000
#define NPAD 100096
#define EE 1600000
#define HID 128
#define FEAT 16
#define INDIM 20
#define NTYPE 4
#define NREL 3
#define LNEPS 1e-5f
#define NB_SCAN 98   // 98 * 1024 >= NN+1

// ---------------- scratch (static device globals; no allocation) ----------------
__device__ float g_x[(size_t)NPAD * HID];
__device__ float g_y[NREL][(size_t)NPAD * HID];
__device__ int   g_deg[NN];
__device__ int   g_off[NN + 1];
__device__ int   g_cur[NN];
__device__ int   g_bsum[NB_SCAN];
__device__ unsigned g_eidx[EE];
__device__ unsigned g_torder[NN];
__device__ int   g_tcnt[NTYPE];
__device__ int   g_tcur[NTYPE];
__device__ float g_pooled[HID];
// pre-swizzled bf16 weight images: 8 matrices (2 layers x {rel0,rel1,rel2,lin}),
// each 64KB = hi[32KB] + lo[32KB]; B[n][k] rows of 256B, chunk-XOR swizzled
__device__ __align__(16) unsigned char g_wimg[8 * 65536];

// ---------------- helpers ----------------
__device__ __forceinline__ unsigned smem_u32(const void* p) {
    unsigned a;
    asm("{ .reg .u64 t; cvta.to.shared.u64 t, %1; cvt.u32.u64 %0, t; }" : "=r"(a) : "l"(p));
    return a;
}
__device__ __forceinline__ unsigned b16(float v) {
    return (unsigned)__bfloat16_as_ushort(__float2bfloat16(v));
}
__device__ __forceinline__ float b16f(unsigned b) {
    return __bfloat162float(__ushort_as_bfloat16((unsigned short)b));
}
// swizzled byte offset inside a [128 rows x 128 bf16] tile with 256B rows:
// 16B chunks, chunk index XORed with (row & 7) -> conflict-free ldmatrix
__device__ __forceinline__ unsigned swzoff(int row, int chunk) {
    return (unsigned)row * 256u + (unsigned)((chunk ^ (row & 7)) << 4);
}

#define LDSM_X4(r0, r1, r2, r3, addr) \
    asm volatile("ldmatrix.sync.aligned.m8n8.x4.shared.b16 {%0,%1,%2,%3}, [%4];" \
                 : "=r"(r0), "=r"(r1), "=r"(r2), "=r"(r3) : "r"(addr))

#define MMA16816(d, a0, a1, a2, a3, b0, b1) \
    asm volatile("mma.sync.aligned.m16n8k16.row.col.f32.bf16.bf16.f32 " \
                 "{%0,%1,%2,%3}, {%4,%5,%6,%7}, {%8,%9}, {%0,%1,%2,%3};" \
                 : "+f"((d)[0]), "+f"((d)[1]), "+f"((d)[2]), "+f"((d)[3]) \
                 : "r"(a0), "r"(a1), "r"(a2), "r"(a3), "r"(b0), "r"(b1))

// ---------------- setup kernels ----------------
__global__ void k_zero_misc() {
    int i = blockIdx.x * blockDim.x + threadIdx.x;
    if (i < NN) g_deg[i] = 0;
    if (i < HID) g_pooled[i] = 0.f;
    if (i < NTYPE) g_tcnt[i] = 0;
}

__global__ void k_deg(const int* __restrict__ dst) {
    int i = blockIdx.x * blockDim.x + threadIdx.x;
    if (i < EE) atomicAdd(&g_deg[dst[i]], 1);
}

__global__ void k_count(const int* __restrict__ nty) {
    int i = blockIdx.x * blockDim.x + threadIdx.x;
    if (i < NN) atomicAdd(&g_tcnt[nty[i]], 1);
}

__global__ void k_toff() {
    if (threadIdx.x == 0) {
        int s = 0;
        for (int t = 0; t < NTYPE; t++) { g_tcur[t] = s; s += g_tcnt[t]; }
    }
}

__global__ void k_tfill(const int* __restrict__ nty) {
    int i = blockIdx.x * blockDim.x + threadIdx.x;
    if (i < NN) {
        int t = nty[i];
        int pos = atomicAdd(&g_tcur[t], 1);
        g_torder[pos] = (unsigned)i | ((unsigned)t << 20);
    }
}

// ---------------- CSR scan ----------------
__global__ __launch_bounds__(1024) void k_scan1() {
    __shared__ int s[1024];
    int b = blockIdx.x, tid = threadIdx.x;
    int i = b * 1024 + tid;
    int v = (i < NN) ? g_deg[i] : 0;
    s[tid] = v;
    __syncthreads();
    for (int off = 1; off < 1024; off <<= 1) {
        int t = (tid >= off) ? s[tid - off] : 0;
        __syncthreads();
        s[tid] += t;
        __syncthreads();
    }
    if (i < NN) g_off[i] = s[tid] - v;
    if (tid == 1023) g_bsum[b] = s[1023];
}

__global__ void k_scan2() {
    if (threadIdx.x == 0) {
        int s = 0;
        for (int b = 0; b < NB_SCAN; b++) { int v = g_bsum[b]; g_bsum[b] = s; s += v; }
    }
}

__global__ __launch_bounds__(1024) void k_scan3() {
    int b = blockIdx.x, i = b * 1024 + threadIdx.x;
    if (i < NN) {
        int val = g_off[i] + g_bsum[b];
        g_off[i] = val;
        g_cur[i] = val;
    }
    if (i == NN) g_off[NN] = EE;
}

__global__ void k_fill(const int* __restrict__ src, const int* __restrict__ dst,
                       const int* __restrict__ et) {
    int e = blockIdx.x * blockDim.x + threadIdx.x;
    if (e < EE) {
        int d = dst[e];
        int pos = atomicAdd(&g_cur[d], 1);
        g_eidx[pos] = (unsigned)src[e] | ((unsigned)et[e] << 17);
    }
}

// ---------------- weight prep: transpose + bf16 hi/lo split + swizzled images ----------------
__global__ void k_wprep(const float* __restrict__ relW, const float* __restrict__ linW) {
    int b = blockIdx.x;                  // 0..7  -> (layer, m)
    int l = b >> 2, m = b & 3;
    const float* W = (m < 3) ? relW + ((size_t)l * 3 + m) * 16384
                             : linW + (size_t)l * 16384;
    unsigned char* img = g_wimg + ((size_t)b << 16);
    // B[n][k] = W[k][n]; one 16B chunk (8 k-values) per iteration
    for (int idx = threadIdx.x; idx < 2048; idx += blockDim.x) {
        int n = idx >> 4, ch = idx & 15;
        unsigned hi[4], lo[4];
        #pragma unroll
        for (int j = 0; j < 4; j++) {
            float v0 = W[(ch * 8 + 2 * j) * HID + n];
            float v1 = W[(ch * 8 + 2 * j + 1) * HID + n];
            unsigned h0 = b16(v0), h1 = b16(v1);
            hi[j] = h0 | (h1 << 16);
            lo[j] = b16(v0 - b16f(h0)) | (b16(v1 - b16f(h1)) << 16);
        }
        unsigned off = swzoff(n, ch);
        *(uint4*)(img + off)         = make_uint4(hi[0], hi[1], hi[2], hi[3]);
        *(uint4*)(img + 32768 + off) = make_uint4(lo[0], lo[1], lo[2], lo[3]);
    }
}

// ---------------- encoder: per-type 2-layer MLP (type-bucketed) ----------------
#define ENC_SMEM_BYTES (129920)
__global__ __launch_bounds__(256) void k_enc(
    const int* __restrict__ z, const float* __restrict__ sd,
    const float* __restrict__ dff, const float* __restrict__ cond,
    const float* __restrict__ mult,
    const float* __restrict__ zemb,
    const float* __restrict__ W1, const float* __restrict__ b1,
    const float* __restrict__ W2, const float* __restrict__ b2)
{
    extern __shared__ __align__(16) float sm[];
    float* sW2  = sm;                 // 128*128
    float* sW1  = sm + 16384;         // 4*20*128
    float* sh1  = sW1 + 10240;        // 32*128
    float* sb1  = sh1 + 4096;         // 4*128
    float* sb2  = sb1 + 512;          // 4*128
    float* sraw = sb2 + 512;          // 32*20
    int*   stype = (int*)(sraw + 640);
    int*   snode = stype + 32;
    int*   sz    = snode + 32;

    int tid = threadIdx.x;
    int n0 = blockIdx.x * 32;

    if (tid < 32) {
        unsigned v = g_torder[n0 + tid];
        int node = v & 0xFFFFF;
        snode[tid] = node;
        stype[tid] = v >> 20;
        sz[tid]    = z[node];
        sraw[tid * INDIM + 16] = sd[node];
        sraw[tid * INDIM + 17] = dff[node];
        sraw[tid * INDIM + 18] = cond[node];
        sraw[tid * INDIM + 19] = mult[node];
    }
    for (int i = tid; i < NTYPE * INDIM * HID; i += 256) sW1[i] = W1[i];
    for (int i = tid; i < NTYPE * HID; i += 256) { sb1[i] = b1[i]; sb2[i] = b2[i]; }
    __syncthreads();
    for (int i = tid; i < 32 * FEAT; i += 256) {
        int li = i / FEAT, k = i % FEAT;
        sraw[li * INDIM + k] = zemb[sz[li] * FEAT + k];
    }
    __syncthreads();

    {
        int c = tid & 127, half = tid >> 7;
        for (int i = half; i < 32; i += 2) {
            int t = stype[i];
            float acc = sb1[t * HID + c];
            #pragma unroll
            for (int k = 0; k < INDIM; k++)
                acc += sraw[i * INDIM + k] * sW1[(t * INDIM + k) * HID + c];
            sh1[i * HID + c] = fmaxf(acc, 0.f);
        }
    }

    int lane = tid & 31, ig = tid >> 5, c0 = lane * 4;
    int tmin = stype[0], tmax = stype[31];
    for (int t = tmin; t <= tmax; t++) {
        __syncthreads();
        const float4* W2t = (const float4*)(W2 + (size_t)t * HID * HID);
        for (int i = tid; i < HID * HID / 4; i += 256) ((float4*)sW2)[i] = W2t[i];
        __syncthreads();
        #pragma unroll
        for (int u = 0; u < 4; u++) {
            int i = ig * 4 + u;
            if (stype[i] != t) continue;
            float4 acc = *(const float4*)&sb2[t * HID + c0];
            const float* h1 = &sh1[i * HID];
            #pragma unroll 4
            for (int k = 0; k < HID; k++) {
                float xv = h1[k];
                float4 w = *(const float4*)&sW2[k * HID + c0];
                acc.x += xv * w.x; acc.y += xv * w.y;
                acc.z += xv * w.z; acc.w += xv * w.w;
            }
            *(float4*)&g_x[(size_t)snode[i] * HID + c0] = acc;
        }
    }
}

// ---------------- gather: per-node, per-relation sums of x[src] (CSR, no atomics) ----------------
__global__ __launch_bounds__(256) void k_gather() {
    int wid = threadIdx.x >> 5, lane = threadIdx.x & 31;
    int node = blockIdx.x * 8 + wid;                    // NN % 8 == 0
    int rs = g_off[node], re = g_off[node + 1];
    float4 a0 = make_float4(0.f, 0.f, 0.f, 0.f);
    float4 a1 = a0, a2 = a0;
    for (int base = rs; base < re; base += 32) {
        int n = min(32, re - base);
        unsigned ep = (base + lane < re) ? g_eidx[base + lane] : 0u;
        for (int j = 0; j < n; j++) {
            unsigned v = __shfl_sync(0xffffffffu, ep, j);
            int s = v & 0x1FFFF;
            int r = v >> 17;
            float4 xv = *(const float4*)&g_x[(size_t)s * HID + lane * 4];
            if (r == 0)      { a0.x += xv.x; a0.y += xv.y; a0.z += xv.z; a0.w += xv.w; }
            else if (r == 1) { a1.x += xv.x; a1.y += xv.y; a1.z += xv.z; a1.w += xv.w; }
            else             { a2.x += xv.x; a2.y += xv.y; a2.z += xv.z; a2.w += xv.w; }
        }
    }
    float inv = 1.f / (float)max(re - rs, 1);
    size_t o = (size_t)node * HID + lane * 4;
    *(float4*)&g_y[0][o] = make_float4(a0.x * inv, a0.y * inv, a0.z * inv, a0.w * inv);
    *(float4*)&g_y[1][o] = make_float4(a1.x * inv, a1.y * inv, a1.z * inv, a1.w * inv);
    *(float4*)&g_y[2][o] = make_float4(a2.x * inv, a2.y * inv, a2.z * inv, a2.w * inv);
}

// ---------------- mma.sync fused 4-GEMM (split-bf16) + bias + LayerNorm ----------------
// Per CTA: 128-node x 128-col tile; D = sum_m A_m @ B_m^T, each via 3 split-bf16 products.
// Warp w owns rows 16w..16w+15; 16 n-tiles of 8 cols.
#define GEMM_SMEM_BYTES (131072)
__global__ __launch_bounds__(256) void k_gemm(
    int layer, const float* __restrict__ linb,
    const float* __restrict__ lng, const float* __restrict__ lnb)
{
    extern __shared__ __align__(16) unsigned char dsm[];
    __shared__ float s_linb[HID], s_lng[HID], s_lnb[HID];

    unsigned char* AH = dsm;              // 32KB
    unsigned char* AL = dsm + 32768;      // 32KB
    unsigned char* BH = dsm + 65536;      // 32KB (hi) + 32KB (lo) contiguous

    int tid = threadIdx.x, lane = tid & 31, w = tid >> 5;
    int n0 = blockIdx.x * 128;

    if (tid < HID) { s_linb[tid] = linb[tid]; s_lng[tid] = lng[tid]; s_lnb[tid] = lnb[tid]; }

    unsigned aHB = smem_u32(AH), aLB = smem_u32(AL);
    unsigned bHB = smem_u32(BH), bLB = bHB + 32768;

    // ldmatrix lane geometry
    int g = lane >> 3, r = lane & 7;
    int rowA = 16 * w + ((g & 1) << 3) + r;          // A: m0/m2 rows 0-7, m1/m3 rows 8-15
    int achS = g >> 1;                               // chunk offset within kstep
    int nOff = ((g >> 1) << 3) + r;                  // B: m0/m1 rows n+0-7, m2/m3 n+8-15
    int bchS = g & 1;

    float acc[16][4];
    #pragma unroll
    for (int t = 0; t < 16; t++)
        acc[t][0] = acc[t][1] = acc[t][2] = acc[t][3] = 0.f;

    int arow = tid >> 1, ahalf = tid & 1;            // staging: half a row per thread

    #pragma unroll 1
    for (int m = 0; m < 4; m++) {
        __syncthreads();   // previous compute done before restaging
        // stage B: linear 64KB copy of pre-swizzled hi+lo image
        {
            const uint4* bsrc = (const uint4*)(g_wimg + (((size_t)layer * 4 + m) << 16));
            uint4* bdst = (uint4*)BH;
            #pragma unroll
            for (int i = 0; i < 16; i++) bdst[tid + 256 * i] = bsrc[tid + 256 * i];
        }
        // stage A: fp32 -> bf16 hi/lo, swizzled chunks
        {
            const float* inp = (m == 0) ? g_y[0] : (m == 1) ? g_y[1]
                             : (m == 2) ? g_y[2] : g_x;
            const float4* asrc = (const float4*)(inp + (size_t)(n0 + arow) * HID + ahalf * 64);
            #pragma unroll
            for (int c = 0; c < 8; c++) {
                float4 v0 = asrc[2 * c], v1 = asrc[2 * c + 1];
                unsigned h0 = b16(v0.x), h1 = b16(v0.y), h2 = b16(v0.z), h3 = b16(v0.w);
                unsigned h4 = b16(v1.x), h5 = b16(v1.y), h6 = b16(v1.z), h7 = b16(v1.w);
                unsigned off = swzoff(arow, ahalf * 8 + c);
                *(uint4*)(AH + off) = make_uint4(h0 | (h1 << 16), h2 | (h3 << 16),
                                                 h4 | (h5 << 16), h6 | (h7 << 16));
                unsigned l0 = b16(v0.x - b16f(h0)), l1 = b16(v0.y - b16f(h1));
                unsigned l2 = b16(v0.z - b16f(h2)), l3 = b16(v0.w - b16f(h3));
                unsigned l4 = b16(v1.x - b16f(h4)), l5 = b16(v1.y - b16f(h5));
                unsigned l6 = b16(v1.z - b16f(h6)), l7 = b16(v1.w - b16f(h7));
                *(uint4*)(AL + off) = make_uint4(l0 | (l1 << 16), l2 | (l3 << 16),
                                                 l4 | (l5 << 16), l6 | (l7 << 16));
            }
        }
        __syncthreads();

        #pragma unroll 2
        for (int ks = 0; ks < 8; ks++) {
            unsigned aoff = swzoff(rowA, 2 * ks + achS);
            unsigned ah0, ah1, ah2, ah3, al0, al1, al2, al3;
            LDSM_X4(ah0, ah1, ah2, ah3, aHB + aoff);
            LDSM_X4(al0, al1, al2, al3, aLB + aoff);
            #pragma unroll
            for (int t = 0; t < 8; t++) {
                int nB = 16 * t + nOff;
                unsigned boff = swzoff(nB, 2 * ks + bchS);
                unsigned bh0, bh1, bh2, bh3, bl0, bl1, bl2, bl3;
                LDSM_X4(bh0, bh1, bh2, bh3, bHB + boff);
                LDSM_X4(bl0, bl1, bl2, bl3, bLB + boff);
                MMA16816(acc[2 * t],     ah0, ah1, ah2, ah3, bh0, bh1);
                MMA16816(acc[2 * t],     al0, al1, al2, al3, bh0, bh1);
                MMA16816(acc[2 * t],     ah0, ah1, ah2, ah3, bl0, bl1);
                MMA16816(acc[2 * t + 1], ah0, ah1, ah2, ah3, bh2, bh3);
                MMA16816(acc[2 * t + 1], al0, al1, al2, al3, bh2, bh3);
                MMA16816(acc[2 * t + 1], ah0, ah1, ah2, ah3, bl2, bl3);
            }
        }
    }

    // epilogue: bias + per-row LayerNorm + write g_x
    // lane quad q = lane&3 owns cols 8t+2q, 8t+2q+1; rows r0 = 16w + lane/4, r1 = r0+8
    {
        int q = lane & 3;
        int r0 = n0 + 16 * w + (lane >> 2), r1 = r0 + 8;
        float s0 = 0.f, s1 = 0.f;
        #pragma unroll
        for (int t = 0; t < 16; t++) {
            int c = 8 * t + 2 * q;
            float bx = s_linb[c], by = s_linb[c + 1];
            acc[t][0] += bx; acc[t][1] += by;
            acc[t][2] += bx; acc[t][3] += by;
            s0 += acc[t][0] + acc[t][1];
            s1 += acc[t][2] + acc[t][3];
        }
        s0 += __shfl_xor_sync(0xffffffffu, s0, 1);
        s0 += __shfl_xor_sync(0xffffffffu, s0, 2);
        s1 += __shfl_xor_sync(0xffffffffu, s1, 1);
        s1 += __shfl_xor_sync(0xffffffffu, s1, 2);
        float mu0 = s0 * (1.f / HID), mu1 = s1 * (1.f / HID);
        float v0 = 0.f, v1 = 0.f;
        #pragma unroll
        for (int t = 0; t < 16; t++) {
            float d0 = acc[t][0] - mu0, d1 = acc[t][1] - mu0;
            float d2 = acc[t][2] - mu1, d3 = acc[t][3] - mu1;
            v0 += d0 * d0 + d1 * d1;
            v1 += d2 * d2 + d3 * d3;
        }
        v0 += __shfl_xor_sync(0xffffffffu, v0, 1);
        v0 += __shfl_xor_sync(0xffffffffu, v0, 2);
        v1 += __shfl_xor_sync(0xffffffffu, v1, 1);
        v1 += __shfl_xor_sync(0xffffffffu, v1, 2);
        float rs0 = rsqrtf(v0 * (1.f / HID) + LNEPS);
        float rs1 = rsqrtf(v1 * (1.f / HID) + LNEPS);
        #pragma unroll
        for (int t = 0; t < 16; t++) {
            int c = 8 * t + 2 * q;
            float gx = s_lng[c], gy = s_lng[c + 1];
            float bx = s_lnb[c], by = s_lnb[c + 1];
            if (r0 < NN) {
                float2 o0 = make_float2((acc[t][0] - mu0) * rs0 * gx + bx,
                                        (acc[t][1] - mu0) * rs0 * gy + by);
                *(float2*)&g_x[(size_t)r0 * HID + c] = o0;
            }
            if (r1 < NN) {
                float2 o1 = make_float2((acc[t][2] - mu1) * rs1 * gx + bx,
                                        (acc[t][3] - mu1) * rs1 * gy + by);
                *(float2*)&g_x[(size_t)r1 * HID + c] = o1;
            }
        }
    }
}

// ---------------- pooling + regressor ----------------
__global__ __launch_bounds__(256) void k_pool() {
    __shared__ float4 spart[256];
    int lane = threadIdx.x & 31, w = threadIdx.x >> 5;
    float4 acc = make_float4(0.f, 0.f, 0.f, 0.f);
    for (int node = blockIdx.x * 8 + w; node < NN; node += gridDim.x * 8) {
        float4 v = *(const float4*)&g_x[(size_t)node * HID + lane * 4];
        acc.x += v.x; acc.y += v.y; acc.z += v.z; acc.w += v.w;
    }
    spart[threadIdx.x] = acc;
    __syncthreads();
    if (w == 0) {
        float4 s = spart[lane];
        #pragma unroll
        for (int q = 1; q < 8; q++) {
            float4 v = spart[q * 32 + lane];
            s.x += v.x; s.y += v.y; s.z += v.z; s.w += v.w;
        }
        atomicAdd(&g_pooled[lane * 4 + 0], s.x);
        atomicAdd(&g_pooled[lane * 4 + 1], s.y);
        atomicAdd(&g_pooled[lane * 4 + 2], s.z);
        atomicAdd(&g_pooled[lane * 4 + 3], s.w);
    }
}

__global__ void k_final(const float* __restrict__ regW,
                        const float* __restrict__ regb, float* __restrict__ out)
{
    int lane = threadIdx.x;
    float4 p = *(const float4*)&g_pooled[lane * 4];
    float4 w = *(const float4*)&regW[lane * 4];
    float s = p.x * w.x + p.y * w.y + p.z * w.z + p.w * w.w;
    #pragma unroll
    for (int o = 16; o; o >>= 1) s += __shfl_xor_sync(0xffffffffu, s, o);
    if (lane == 0) out[0] = s * (1.f / NN) + regb[0];
}

// ---------------- host launcher ----------------
extern "C" void kernel_launch(void* const* d_in, const int* in_sizes, int n_in,
                              void* d_out, int out_size)
{
    const int*   z    = (const int*)  d_in[0];
    const float* sd   = (const float*)d_in[1];
    const float* dff  = (const float*)d_in[2];
    const float* cond = (const float*)d_in[3];
    const float* mult = (const float*)d_in[4];
    const int*   nty  = (const int*)  d_in[5];
    const int*   ei   = (const int*)  d_in[6];
    const int*   et   = (const int*)  d_in[7];
    const float* zemb = (const float*)d_in[8];
    const float* eW1  = (const float*)d_in[9];
    const float* eb1  = (const float*)d_in[10];
    const float* eW2  = (const float*)d_in[11];
    const float* eb2  = (const float*)d_in[12];
    const float* linW = (const float*)d_in[13];
    const float* linb = (const float*)d_in[14];
    const float* relW = (const float*)d_in[15];
    const float* lng  = (const float*)d_in[16];
    const float* lnb  = (const float*)d_in[17];
    const float* regW = (const float*)d_in[18];
    const float* regb = (const float*)d_in[19];
    const int* src = ei, * dst = ei + EE;

    cudaFuncSetAttribute(k_enc, cudaFuncAttributeMaxDynamicSharedMemorySize, ENC_SMEM_BYTES);
    cudaFuncSetAttribute(k_gemm, cudaFuncAttributeMaxDynamicSharedMemorySize, GEMM_SMEM_BYTES);

    // setup: degree histogram, type buckets, CSR, weight images
    k_zero_misc<<<(NN + 255) / 256, 256>>>();
    k_deg<<<(EE + 255) / 256, 256>>>(dst);
    k_count<<<(NN + 255) / 256, 256>>>(nty);
    k_toff<<<1, 32>>>();
    k_tfill<<<(NN + 255) / 256, 256>>>(nty);
    k_scan1<<<NB_SCAN, 1024>>>();
    k_scan2<<<1, 32>>>();
    k_scan3<<<NB_SCAN, 1024>>>();
    k_fill<<<(EE + 255) / 256, 256>>>(src, dst, et);
    k_wprep<<<8, 256>>>(relW, linW);

    // encoder
    k_enc<<<NN / 32, 256, ENC_SMEM_BYTES>>>(z, sd, dff, cond, mult, zemb,
                                            eW1, eb1, eW2, eb2);
    // GNN layers
    for (int l = 0; l < 2; l++) {
        k_gather<<<NN / 8, 256>>>();
        k_gemm<<<NPAD / 128, 256, GEMM_SMEM_BYTES>>>(l, linb + (size_t)l * HID,
                                                     lng + (size_t)l * HID,
                                                     lnb + (size_t)l * HID);
    }
    k_pool<<<512, 256>>>();
    k_final<<<1, 32>>>(regW, regb, (float*)d_out);
}

// round 12
// speedup vs baseline: 3.0080x; 1.2144x over previous
#include <cuda_runtime.h>
#include <cuda_bf16.h>

#define NN 100000
#define NPAD 100096
#define EE 1600000
#define HID 128
#define FEAT 16
#define INDIM 20
#define NTYPE 4
#define NREL 3
#define LNEPS 1e-5f
#define NB_SCAN 98   // 98 * 1024 >= NN+1

// ---------------- scratch (static device globals; no allocation) ----------------
__device__ float g_x[(size_t)NPAD * HID];
__device__ float g_y[NREL][(size_t)NPAD * HID];
__device__ int   g_deg[NN];
__device__ int   g_off[NN + 1];
__device__ int   g_cur[NN];
__device__ int   g_bsum[NB_SCAN];
__device__ unsigned g_eidx[EE];
__device__ unsigned g_torder[NPAD];
__device__ int   g_tcnt[NTYPE];
__device__ int   g_tcur[NTYPE];
__device__ float g_pooled[HID];
// pre-swizzled bf16 weight images: 8 matrices (2 layers x {rel0,rel1,rel2,lin}),
// each 64KB = hi[32KB] + lo[32KB]; B[n][k] rows of 256B, chunk-XOR swizzled
__device__ __align__(16) unsigned char g_wimg[8 * 65536];

// ---------------- helpers ----------------
__device__ __forceinline__ unsigned smem_u32(const void* p) {
    unsigned a;
    asm("{ .reg .u64 t; cvta.to.shared.u64 t, %1; cvt.u32.u64 %0, t; }" : "=r"(a) : "l"(p));
    return a;
}
__device__ __forceinline__ unsigned b16(float v) {
    return (unsigned)__bfloat16_as_ushort(__float2bfloat16(v));
}
__device__ __forceinline__ float b16f(unsigned b) {
    return __bfloat162float(__ushort_as_bfloat16((unsigned short)b));
}
__device__ __forceinline__ unsigned swzoff(int row, int chunk) {
    return (unsigned)row * 256u + (unsigned)((chunk ^ (row & 7)) << 4);
}
__device__ __forceinline__ void ffma2(unsigned long long& d, unsigned long long a,
                                      unsigned long long b) {
    asm("fma.rn.f32x2 %0, %1, %2, %3;" : "=l"(d) : "l"(a), "l"(b), "l"(d));
}
__device__ __forceinline__ float pairsum(unsigned long long v) {
    float2 f = *reinterpret_cast<float2*>(&v);
    return f.x + f.y;
}
__device__ __forceinline__ unsigned long long packlo(float v) {
    return (unsigned long long)__float_as_uint(v);
}

#define LDSM_X4(r0, r1, r2, r3, addr) \
    asm volatile("ldmatrix.sync.aligned.m8n8.x4.shared.b16 {%0,%1,%2,%3}, [%4];" \
                 : "=r"(r0), "=r"(r1), "=r"(r2), "=r"(r3) : "r"(addr))

#define MMA16816(d, a0, a1, a2, a3, b0, b1) \
    asm volatile("mma.sync.aligned.m16n8k16.row.col.f32.bf16.bf16.f32 " \
                 "{%0,%1,%2,%3}, {%4,%5,%6,%7}, {%8,%9}, {%0,%1,%2,%3};" \
                 : "+f"((d)[0]), "+f"((d)[1]), "+f"((d)[2]), "+f"((d)[3]) \
                 : "r"(a0), "r"(a1), "r"(a2), "r"(a3), "r"(b0), "r"(b1))

// ---------------- setup kernels ----------------
// fused degree histogram + node-type count (buffers pre-zeroed via cudaMemsetAsync)
__global__ void k_hist(const int* __restrict__ dst, const int* __restrict__ nty) {
    int i = blockIdx.x * blockDim.x + threadIdx.x;
    if (i < EE) atomicAdd(&g_deg[dst[i]], 1);
    if (i < NN) atomicAdd(&g_tcnt[nty[i]], 1);
}

__global__ void k_toff() {
    if (threadIdx.x == 0) {
        int s = 0;
        for (int t = 0; t < NTYPE; t++) { g_tcur[t] = s; s += g_tcnt[t]; }
    }
}

__global__ void k_tfill(const int* __restrict__ nty) {
    int i = blockIdx.x * blockDim.x + threadIdx.x;
    if (i < NN) {
        int t = nty[i];
        int pos = atomicAdd(&g_tcur[t], 1);
        g_torder[pos] = (unsigned)i | ((unsigned)t << 20);
    } else if (i < NPAD) {
        g_torder[i] = (unsigned)(NN - 1) | (3u << 20);   // padding: safe node, max type
    }
}

// ---------------- encoder: per-type 2-layer MLP, 64-node type-sorted tiles ----------------
// phase C uses the conflict-free f32x2 engine (k-pair interleaved W2 in smem)
#define ENC_SMEM_BYTES (149504)
__global__ __launch_bounds__(256, 1) void k_enc(
    const int* __restrict__ z, const float* __restrict__ sd,
    const float* __restrict__ dff, const float* __restrict__ cond,
    const float* __restrict__ mult,
    const float* __restrict__ zemb,
    const float* __restrict__ W1, const float* __restrict__ b1,
    const float* __restrict__ W2, const float* __restrict__ b2)
{
    extern __shared__ __align__(16) float sm[];
    float2* sw2i = (float2*)sm;            // 16384 floats: interleaved W2 (one type)
    float*  sh1  = sm + 16384;             // 64*128
    float*  sW1  = sm + 24576;             // 4*20*128
    float*  sb1  = sm + 34816;             // 4*128
    float*  sb2  = sm + 35328;             // 4*128
    float*  sraw = sm + 35840;             // 64*20
    int*    stype = (int*)(sm + 37120);    // 64
    int*    snode = stype + 64;            // 64
    int*    sz    = snode + 64;            // 64

    int tid = threadIdx.x;
    int n0 = blockIdx.x * 64;

    if (tid < 64) {
        unsigned v = g_torder[n0 + tid];
        int node = v & 0xFFFFF;
        snode[tid] = node;
        stype[tid] = v >> 20;
        sz[tid]    = z[node];
        sraw[tid * INDIM + 16] = sd[node];
        sraw[tid * INDIM + 17] = dff[node];
        sraw[tid * INDIM + 18] = cond[node];
        sraw[tid * INDIM + 19] = mult[node];
    }
    for (int i = tid; i < NTYPE * INDIM * HID; i += 256) sW1[i] = W1[i];
    for (int i = tid; i < NTYPE * HID; i += 256) { sb1[i] = b1[i]; sb2[i] = b2[i]; }
    __syncthreads();
    for (int i = tid; i < 64 * FEAT; i += 256) {
        int li = i / FEAT, k = i % FEAT;
        sraw[li * INDIM + k] = zemb[sz[li] * FEAT + k];
    }
    __syncthreads();

    // phase B: h1 = relu(raw @ W1[t] + b1[t]) for 64 nodes
    {
        int c = tid & 127, half = tid >> 7;
        for (int i = half; i < 64; i += 2) {
            int t = stype[i];
            float acc = sb1[t * HID + c];
            #pragma unroll
            for (int k = 0; k < INDIM; k++)
                acc += sraw[i * INDIM + k] * sW1[(t * INDIM + k) * HID + c];
            sh1[i * HID + c] = fmaxf(acc, 0.f);
        }
    }

    // phase C: x = h1 @ W2[t] + b2[t], f32x2 engine; blocks are type-sorted so
    // usually a single type pass (boundary blocks: 2).
    int lane = tid & 31, w = tid >> 5, c0 = lane * 4;
    int nodebase = w * 8;
    int tmin = stype[0], tmax = stype[63];
    for (int t = tmin; t <= tmax; t++) {
        __syncthreads();   // sh1 ready (first iter) / previous pass done reading sw2i
        const float* W2t = W2 + (size_t)t * HID * HID;
        for (int i = tid; i < 2048; i += 256) {
            int kp = i >> 5, cg = i & 31;
            float4 a = *(const float4*)&W2t[(2 * kp) * HID + cg * 4];
            float4 b = *(const float4*)&W2t[(2 * kp + 1) * HID + cg * 4];
            float2* base = &sw2i[kp * 128];
            *(float4*)&base[cg * 2]      = make_float4(a.x, b.x, a.y, b.y);
            *(float4*)&base[64 + cg * 2] = make_float4(a.z, b.z, a.w, b.w);
        }
        __syncthreads();

        unsigned long long acc[8][4];
        {
            unsigned long long c0v = packlo(sb2[t * HID + c0 + 0]);
            unsigned long long c1v = packlo(sb2[t * HID + c0 + 1]);
            unsigned long long c2v = packlo(sb2[t * HID + c0 + 2]);
            unsigned long long c3v = packlo(sb2[t * HID + c0 + 3]);
            #pragma unroll
            for (int n = 0; n < 8; n++) {
                acc[n][0] = c0v; acc[n][1] = c1v; acc[n][2] = c2v; acc[n][3] = c3v;
            }
        }
        #pragma unroll 4
        for (int c4 = 0; c4 < 32; c4++) {
            const float2* rA = &sw2i[(2 * c4) * 128];
            const float2* rB = &sw2i[(2 * c4 + 1) * 128];
            ulonglong2 a0 = *(const ulonglong2*)&rA[lane * 2];
            ulonglong2 a1 = *(const ulonglong2*)&rA[64 + lane * 2];
            ulonglong2 b0 = *(const ulonglong2*)&rB[lane * 2];
            ulonglong2 b1 = *(const ulonglong2*)&rB[64 + lane * 2];
            #pragma unroll
            for (int n = 0; n < 8; n++) {
                ulonglong2 xq = *(const ulonglong2*)&sh1[(nodebase + n) * HID + c4 * 4];
                ffma2(acc[n][0], xq.x, a0.x);
                ffma2(acc[n][1], xq.x, a0.y);
                ffma2(acc[n][2], xq.x, a1.x);
                ffma2(acc[n][3], xq.x, a1.y);
                ffma2(acc[n][0], xq.y, b0.x);
                ffma2(acc[n][1], xq.y, b0.y);
                ffma2(acc[n][2], xq.y, b1.x);
                ffma2(acc[n][3], xq.y, b1.y);
            }
        }
        #pragma unroll
        for (int n = 0; n < 8; n++) {
            int i = nodebase + n;
            if (stype[i] == t && n0 + i < NN) {
                float4 o = make_float4(pairsum(acc[n][0]), pairsum(acc[n][1]),
                                       pairsum(acc[n][2]), pairsum(acc[n][3]));
                *(float4*)&g_x[(size_t)snode[i] * HID + c0] = o;
            }
        }
    }
}

// ---------------- CSR scan ----------------
__global__ __launch_bounds__(1024) void k_scan1() {
    __shared__ int s[1024];
    int b = blockIdx.x, tid = threadIdx.x;
    int i = b * 1024 + tid;
    int v = (i < NN) ? g_deg[i] : 0;
    s[tid] = v;
    __syncthreads();
    for (int off = 1; off < 1024; off <<= 1) {
        int t = (tid >= off) ? s[tid - off] : 0;
        __syncthreads();
        s[tid] += t;
        __syncthreads();
    }
    if (i < NN) g_off[i] = s[tid] - v;
    if (tid == 1023) g_bsum[b] = s[1023];
}

__global__ void k_scan2() {
    if (threadIdx.x == 0) {
        int s = 0;
        for (int b = 0; b < NB_SCAN; b++) { int v = g_bsum[b]; g_bsum[b] = s; s += v; }
    }
}

__global__ __launch_bounds__(1024) void k_scan3() {
    int b = blockIdx.x, i = b * 1024 + threadIdx.x;
    if (i < NN) {
        int val = g_off[i] + g_bsum[b];
        g_off[i] = val;
        g_cur[i] = val;
    }
    if (i == NN) g_off[NN] = EE;
}

__global__ void k_fill(const int* __restrict__ src, const int* __restrict__ dst,
                       const int* __restrict__ et) {
    int e = blockIdx.x * blockDim.x + threadIdx.x;
    if (e < EE) {
        int d = dst[e];
        int pos = atomicAdd(&g_cur[d], 1);
        g_eidx[pos] = (unsigned)src[e] | ((unsigned)et[e] << 17);
    }
}

// ---------------- weight prep: transpose + bf16 hi/lo split + swizzled images ----------------
__global__ void k_wprep(const float* __restrict__ relW, const float* __restrict__ linW) {
    int b = blockIdx.x;                  // 0..7  -> (layer, m)
    int l = b >> 2, m = b & 3;
    const float* W = (m < 3) ? relW + ((size_t)l * 3 + m) * 16384
                             : linW + (size_t)l * 16384;
    unsigned char* img = g_wimg + ((size_t)b << 16);
    for (int idx = threadIdx.x; idx < 2048; idx += blockDim.x) {
        int n = idx >> 4, ch = idx & 15;
        unsigned hi[4], lo[4];
        #pragma unroll
        for (int j = 0; j < 4; j++) {
            float v0 = W[(ch * 8 + 2 * j) * HID + n];
            float v1 = W[(ch * 8 + 2 * j + 1) * HID + n];
            unsigned h0 = b16(v0), h1 = b16(v1);
            hi[j] = h0 | (h1 << 16);
            lo[j] = b16(v0 - b16f(h0)) | (b16(v1 - b16f(h1)) << 16);
        }
        unsigned off = swzoff(n, ch);
        *(uint4*)(img + off)         = make_uint4(hi[0], hi[1], hi[2], hi[3]);
        *(uint4*)(img + 32768 + off) = make_uint4(lo[0], lo[1], lo[2], lo[3]);
    }
}

// ---------------- gather: per-node per-relation sums (CSR, unroll-4 for MLP) ----------------
__device__ __forceinline__ void acc_rel(float4& a0, float4& a1, float4& a2,
                                        unsigned r, float4 xv) {
    if (r == 0)      { a0.x += xv.x; a0.y += xv.y; a0.z += xv.z; a0.w += xv.w; }
    else if (r == 1) { a1.x += xv.x; a1.y += xv.y; a1.z += xv.z; a1.w += xv.w; }
    else             { a2.x += xv.x; a2.y += xv.y; a2.z += xv.z; a2.w += xv.w; }
}

__global__ __launch_bounds__(256) void k_gather() {
    int wid = threadIdx.x >> 5, lane = threadIdx.x & 31;
    int node = blockIdx.x * 8 + wid;                    // NN % 8 == 0
    int rs = g_off[node], re = g_off[node + 1];
    int cb = lane * 4;
    float4 a0 = make_float4(0.f, 0.f, 0.f, 0.f);
    float4 a1 = a0, a2 = a0;
    for (int base = rs; base < re; base += 32) {
        int n = min(32, re - base);
        unsigned ep = (base + lane < re) ? g_eidx[base + lane] : 0u;
        int j = 0;
        #pragma unroll 1
        for (; j + 4 <= n; j += 4) {
            unsigned v0 = __shfl_sync(0xffffffffu, ep, j);
            unsigned v1 = __shfl_sync(0xffffffffu, ep, j + 1);
            unsigned v2 = __shfl_sync(0xffffffffu, ep, j + 2);
            unsigned v3 = __shfl_sync(0xffffffffu, ep, j + 3);
            float4 x0 = *(const float4*)&g_x[(size_t)(v0 & 0x1FFFF) * HID + cb];
            float4 x1 = *(const float4*)&g_x[(size_t)(v1 & 0x1FFFF) * HID + cb];
            float4 x2 = *(const float4*)&g_x[(size_t)(v2 & 0x1FFFF) * HID + cb];
            float4 x3 = *(const float4*)&g_x[(size_t)(v3 & 0x1FFFF) * HID + cb];
            acc_rel(a0, a1, a2, v0 >> 17, x0);
            acc_rel(a0, a1, a2, v1 >> 17, x1);
            acc_rel(a0, a1, a2, v2 >> 17, x2);
            acc_rel(a0, a1, a2, v3 >> 17, x3);
        }
        for (; j < n; j++) {
            unsigned v = __shfl_sync(0xffffffffu, ep, j);
            float4 xv = *(const float4*)&g_x[(size_t)(v & 0x1FFFF) * HID + cb];
            acc_rel(a0, a1, a2, v >> 17, xv);
        }
    }
    float inv = 1.f / (float)max(re - rs, 1);
    size_t o = (size_t)node * HID + cb;
    *(float4*)&g_y[0][o] = make_float4(a0.x * inv, a0.y * inv, a0.z * inv, a0.w * inv);
    *(float4*)&g_y[1][o] = make_float4(a1.x * inv, a1.y * inv, a1.z * inv, a1.w * inv);
    *(float4*)&g_y[2][o] = make_float4(a2.x * inv, a2.y * inv, a2.z * inv, a2.w * inv);
}

// ---------------- mma.sync fused 4-GEMM (split-bf16) + bias + LayerNorm ----------------
#define GEMM_SMEM_BYTES (131072)
__global__ __launch_bounds__(256) void k_gemm(
    int layer, const float* __restrict__ linb,
    const float* __restrict__ lng, const float* __restrict__ lnb)
{
    extern __shared__ __align__(16) unsigned char dsm[];
    __shared__ float s_linb[HID], s_lng[HID], s_lnb[HID];

    unsigned char* AH = dsm;              // 32KB
    unsigned char* AL = dsm + 32768;      // 32KB
    unsigned char* BH = dsm + 65536;      // 32KB (hi) + 32KB (lo) contiguous

    int tid = threadIdx.x, lane = tid & 31, w = tid >> 5;
    int n0 = blockIdx.x * 128;

    if (tid < HID) { s_linb[tid] = linb[tid]; s_lng[tid] = lng[tid]; s_lnb[tid] = lnb[tid]; }

    unsigned aHB = smem_u32(AH), aLB = smem_u32(AL);
    unsigned bHB = smem_u32(BH), bLB = bHB + 32768;

    int g = lane >> 3, r = lane & 7;
    int rowA = 16 * w + ((g & 1) << 3) + r;
    int achS = g >> 1;
    int nOff = ((g >> 1) << 3) + r;
    int bchS = g & 1;

    float acc[16][4];
    #pragma unroll
    for (int t = 0; t < 16; t++)
        acc[t][0] = acc[t][1] = acc[t][2] = acc[t][3] = 0.f;

    int arow = tid >> 1, ahalf = tid & 1;

    #pragma unroll 1
    for (int m = 0; m < 4; m++) {
        __syncthreads();
        {
            const uint4* bsrc = (const uint4*)(g_wimg + (((size_t)layer * 4 + m) << 16));
            uint4* bdst = (uint4*)BH;
            #pragma unroll
            for (int i = 0; i < 16; i++) bdst[tid + 256 * i] = bsrc[tid + 256 * i];
        }
        {
            const float* inp = (m == 0) ? g_y[0] : (m == 1) ? g_y[1]
                             : (m == 2) ? g_y[2] : g_x;
            const float4* asrc = (const float4*)(inp + (size_t)(n0 + arow) * HID + ahalf * 64);
            #pragma unroll
            for (int c = 0; c < 8; c++) {
                float4 v0 = asrc[2 * c], v1 = asrc[2 * c + 1];
                unsigned h0 = b16(v0.x), h1 = b16(v0.y), h2 = b16(v0.z), h3 = b16(v0.w);
                unsigned h4 = b16(v1.x), h5 = b16(v1.y), h6 = b16(v1.z), h7 = b16(v1.w);
                unsigned off = swzoff(arow, ahalf * 8 + c);
                *(uint4*)(AH + off) = make_uint4(h0 | (h1 << 16), h2 | (h3 << 16),
                                                 h4 | (h5 << 16), h6 | (h7 << 16));
                unsigned l0 = b16(v0.x - b16f(h0)), l1 = b16(v0.y - b16f(h1));
                unsigned l2 = b16(v0.z - b16f(h2)), l3 = b16(v0.w - b16f(h3));
                unsigned l4 = b16(v1.x - b16f(h4)), l5 = b16(v1.y - b16f(h5));
                unsigned l6 = b16(v1.z - b16f(h6)), l7 = b16(v1.w - b16f(h7));
                *(uint4*)(AL + off) = make_uint4(l0 | (l1 << 16), l2 | (l3 << 16),
                                                 l4 | (l5 << 16), l6 | (l7 << 16));
            }
        }
        __syncthreads();

        #pragma unroll 2
        for (int ks = 0; ks < 8; ks++) {
            unsigned aoff = swzoff(rowA, 2 * ks + achS);
            unsigned ah0, ah1, ah2, ah3, al0, al1, al2, al3;
            LDSM_X4(ah0, ah1, ah2, ah3, aHB + aoff);
            LDSM_X4(al0, al1, al2, al3, aLB + aoff);
            #pragma unroll
            for (int t = 0; t < 8; t++) {
                int nB = 16 * t + nOff;
                unsigned boff = swzoff(nB, 2 * ks + bchS);
                unsigned bh0, bh1, bh2, bh3, bl0, bl1, bl2, bl3;
                LDSM_X4(bh0, bh1, bh2, bh3, bHB + boff);
                LDSM_X4(bl0, bl1, bl2, bl3, bLB + boff);
                MMA16816(acc[2 * t],     ah0, ah1, ah2, ah3, bh0, bh1);
                MMA16816(acc[2 * t],     al0, al1, al2, al3, bh0, bh1);
                MMA16816(acc[2 * t],     ah0, ah1, ah2, ah3, bl0, bl1);
                MMA16816(acc[2 * t + 1], ah0, ah1, ah2, ah3, bh2, bh3);
                MMA16816(acc[2 * t + 1], al0, al1, al2, al3, bh2, bh3);
                MMA16816(acc[2 * t + 1], ah0, ah1, ah2, ah3, bl2, bl3);
            }
        }
    }

    {
        int q = lane & 3;
        int r0 = n0 + 16 * w + (lane >> 2), r1 = r0 + 8;
        float s0 = 0.f, s1 = 0.f;
        #pragma unroll
        for (int t = 0; t < 16; t++) {
            int c = 8 * t + 2 * q;
            float bx = s_linb[c], by = s_linb[c + 1];
            acc[t][0] += bx; acc[t][1] += by;
            acc[t][2] += bx; acc[t][3] += by;
            s0 += acc[t][0] + acc[t][1];
            s1 += acc[t][2] + acc[t][3];
        }
        s0 += __shfl_xor_sync(0xffffffffu, s0, 1);
        s0 += __shfl_xor_sync(0xffffffffu, s0, 2);
        s1 += __shfl_xor_sync(0xffffffffu, s1, 1);
        s1 += __shfl_xor_sync(0xffffffffu, s1, 2);
        float mu0 = s0 * (1.f / HID), mu1 = s1 * (1.f / HID);
        float v0 = 0.f, v1 = 0.f;
        #pragma unroll
        for (int t = 0; t < 16; t++) {
            float d0 = acc[t][0] - mu0, d1 = acc[t][1] - mu0;
            float d2 = acc[t][2] - mu1, d3 = acc[t][3] - mu1;
            v0 += d0 * d0 + d1 * d1;
            v1 += d2 * d2 + d3 * d3;
        }
        v0 += __shfl_xor_sync(0xffffffffu, v0, 1);
        v0 += __shfl_xor_sync(0xffffffffu, v0, 2);
        v1 += __shfl_xor_sync(0xffffffffu, v1, 1);
        v1 += __shfl_xor_sync(0xffffffffu, v1, 2);
        float rs0 = rsqrtf(v0 * (1.f / HID) + LNEPS);
        float rs1 = rsqrtf(v1 * (1.f / HID) + LNEPS);
        #pragma unroll
        for (int t = 0; t < 16; t++) {
            int c = 8 * t + 2 * q;
            float gx = s_lng[c], gy = s_lng[c + 1];
            float bx = s_lnb[c], by = s_lnb[c + 1];
            if (r0 < NN) {
                float2 o0 = make_float2((acc[t][0] - mu0) * rs0 * gx + bx,
                                        (acc[t][1] - mu0) * rs0 * gy + by);
                *(float2*)&g_x[(size_t)r0 * HID + c] = o0;
            }
            if (r1 < NN) {
                float2 o1 = make_float2((acc[t][2] - mu1) * rs1 * gx + bx,
                                        (acc[t][3] - mu1) * rs1 * gy + by);
                *(float2*)&g_x[(size_t)r1 * HID + c] = o1;
            }
        }
    }
}

// ---------------- pooling + regressor ----------------
__global__ __launch_bounds__(256) void k_pool() {
    __shared__ float4 spart[256];
    int lane = threadIdx.x & 31, w = threadIdx.x >> 5;
    float4 acc = make_float4(0.f, 0.f, 0.f, 0.f);
    for (int node = blockIdx.x * 8 + w; node < NN; node += gridDim.x * 8) {
        float4 v = *(const float4*)&g_x[(size_t)node * HID + lane * 4];
        acc.x += v.x; acc.y += v.y; acc.z += v.z; acc.w += v.w;
    }
    spart[threadIdx.x] = acc;
    __syncthreads();
    if (w == 0) {
        float4 s = spart[lane];
        #pragma unroll
        for (int q = 1; q < 8; q++) {
            float4 v = spart[q * 32 + lane];
            s.x += v.x; s.y += v.y; s.z += v.z; s.w += v.w;
        }
        atomicAdd(&g_pooled[lane * 4 + 0], s.x);
        atomicAdd(&g_pooled[lane * 4 + 1], s.y);
        atomicAdd(&g_pooled[lane * 4 + 2], s.z);
        atomicAdd(&g_pooled[lane * 4 + 3], s.w);
    }
}

__global__ void k_final(const float* __restrict__ regW,
                        const float* __restrict__ regb, float* __restrict__ out)
{
    int lane = threadIdx.x;
    float4 p = *(const float4*)&g_pooled[lane * 4];
    float4 w = *(const float4*)&regW[lane * 4];
    float s = p.x * w.x + p.y * w.y + p.z * w.z + p.w * w.w;
    #pragma unroll
    for (int o = 16; o; o >>= 1) s += __shfl_xor_sync(0xffffffffu, s, o);
    if (lane == 0) out[0] = s * (1.f / NN) + regb[0];
}

// ---------------- host launcher ----------------
extern "C" void kernel_launch(void* const* d_in, const int* in_sizes, int n_in,
                              void* d_out, int out_size)
{
    const int*   z    = (const int*)  d_in[0];
    const float* sd   = (const float*)d_in[1];
    const float* dff  = (const float*)d_in[2];
    const float* cond = (const float*)d_in[3];
    const float* mult = (const float*)d_in[4];
    const int*   nty  = (const int*)  d_in[5];
    const int*   ei   = (const int*)  d_in[6];
    const int*   et   = (const int*)  d_in[7];
    const float* zemb = (const float*)d_in[8];
    const float* eW1  = (const float*)d_in[9];
    const float* eb1  = (const float*)d_in[10];
    const float* eW2  = (const float*)d_in[11];
    const float* eb2  = (const float*)d_in[12];
    const float* linW = (const float*)d_in[13];
    const float* linb = (const float*)d_in[14];
    const float* relW = (const float*)d_in[15];
    const float* lng  = (const float*)d_in[16];
    const float* lnb  = (const float*)d_in[17];
    const float* regW = (const float*)d_in[18];
    const float* regb = (const float*)d_in[19];
    const int* src = ei, * dst = ei + EE;

    cudaFuncSetAttribute(k_enc, cudaFuncAttributeMaxDynamicSharedMemorySize, ENC_SMEM_BYTES);
    cudaFuncSetAttribute(k_gemm, cudaFuncAttributeMaxDynamicSharedMemorySize, GEMM_SMEM_BYTES);

    // zero histogram buffers via async memset (graph-capturable, no launches)
    void *p_deg = nullptr, *p_tcnt = nullptr, *p_pooled = nullptr;
    cudaGetSymbolAddress(&p_deg, g_deg);
    cudaGetSymbolAddress(&p_tcnt, g_tcnt);
    cudaGetSymbolAddress(&p_pooled, g_pooled);
    cudaMemsetAsync(p_deg, 0, (size_t)NN * sizeof(int));
    cudaMemsetAsync(p_tcnt, 0, NTYPE * sizeof(int));
    cudaMemsetAsync(p_pooled, 0, HID * sizeof(float));

    // type bucketing + encoder first (k_enc lands at kernel-launch index 3 for ncu)
    k_hist<<<(EE + 255) / 256, 256>>>(dst, nty);
    k_toff<<<1, 32>>>();
    k_tfill<<<(NPAD + 255) / 256, 256>>>(nty);
    k_enc<<<NPAD / 64, 256, ENC_SMEM_BYTES>>>(z, sd, dff, cond, mult, zemb,
                                              eW1, eb1, eW2, eb2);
    // CSR + weight images
    k_scan1<<<NB_SCAN, 1024>>>();
    k_scan2<<<1, 32>>>();
    k_scan3<<<NB_SCAN, 1024>>>();
    k_fill<<<(EE + 255) / 256, 256>>>(src, dst, et);
    k_wprep<<<8, 256>>>(relW, linW);

    // GNN layers
    for (int l = 0; l < 2; l++) {
        k_gather<<<NN / 8, 256>>>();
        k_gemm<<<NPAD / 128, 256, GEMM_SMEM_BYTES>>>(l, linb + (size_t)l * HID,
                                                     lng + (size_t)l * HID,
                                                     lnb + (size_t)l * HID);
    }
    k_pool<<<512, 256>>>();
    k_final<<<1, 32>>>(regW, regb, (float*)d_out);
}

// round 13
// speedup vs baseline: 3.5392x; 1.1766x over previous
#include <cuda_runtime.h>
#include <cuda_bf16.h>

#define NN 100000
#define NPAD 100096
#define EE 1600000
#define HID 128
#define FEAT 16
#define INDIM 20
#define NTYPE 4
#define NREL 3
#define LNEPS 1e-5f
#define NB_SCAN 98   // 98 * 1024 >= NN+1

// ---------------- scratch (static device globals; no allocation) ----------------
__device__ float g_x[(size_t)NPAD * HID];
__device__ float g_y[NREL][(size_t)NPAD * HID];
__device__ int   g_deg[NN];
__device__ int   g_off[NN + 1];
__device__ int   g_cur[NN];
__device__ int   g_bsum[NB_SCAN];
__device__ unsigned g_eidx[EE];
__device__ unsigned g_torder[NPAD];
__device__ int   g_tcnt[NTYPE];
__device__ int   g_tcur[NTYPE];
__device__ float g_pooled[HID];
// pre-swizzled bf16 weight images: 8 matrices (2 layers x {rel0,rel1,rel2,lin}),
// each 64KB = hi[32KB] + lo[32KB]; B[n][k] rows of 256B, chunk-XOR swizzled
__device__ __align__(16) unsigned char g_wimg[8 * 65536];

// ---------------- helpers ----------------
__device__ __forceinline__ unsigned smem_u32(const void* p) {
    unsigned a;
    asm("{ .reg .u64 t; cvta.to.shared.u64 t, %1; cvt.u32.u64 %0, t; }" : "=r"(a) : "l"(p));
    return a;
}
__device__ __forceinline__ unsigned b16(float v) {
    return (unsigned)__bfloat16_as_ushort(__float2bfloat16(v));
}
__device__ __forceinline__ float b16f(unsigned b) {
    return __bfloat162float(__ushort_as_bfloat16((unsigned short)b));
}
__device__ __forceinline__ unsigned swzoff(int row, int chunk) {
    return (unsigned)row * 256u + (unsigned)((chunk ^ (row & 7)) << 4);
}
__device__ __forceinline__ void ffma2(unsigned long long& d, unsigned long long a,
                                      unsigned long long b) {
    asm("fma.rn.f32x2 %0, %1, %2, %3;" : "=l"(d) : "l"(a), "l"(b), "l"(d));
}
__device__ __forceinline__ float pairsum(unsigned long long v) {
    float2 f = *reinterpret_cast<float2*>(&v);
    return f.x + f.y;
}
__device__ __forceinline__ unsigned long long packlo(float v) {
    return (unsigned long long)__float_as_uint(v);
}

#define LDSM_X4(r0, r1, r2, r3, addr) \
    asm volatile("ldmatrix.sync.aligned.m8n8.x4.shared.b16 {%0,%1,%2,%3}, [%4];" \
                 : "=r"(r0), "=r"(r1), "=r"(r2), "=r"(r3) : "r"(addr))

#define MMA16816(d, a0, a1, a2, a3, b0, b1) \
    asm volatile("mma.sync.aligned.m16n8k16.row.col.f32.bf16.bf16.f32 " \
                 "{%0,%1,%2,%3}, {%4,%5,%6,%7}, {%8,%9}, {%0,%1,%2,%3};" \
                 : "+f"((d)[0]), "+f"((d)[1]), "+f"((d)[2]), "+f"((d)[3]) \
                 : "r"(a0), "r"(a1), "r"(a2), "r"(a3), "r"(b0), "r"(b1))

// ---------------- setup kernels ----------------
__global__ void k_hist(const int* __restrict__ dst, const int* __restrict__ nty) {
    int i = blockIdx.x * blockDim.x + threadIdx.x;
    if (i < EE) atomicAdd(&g_deg[dst[i]], 1);
    if (i < NN) atomicAdd(&g_tcnt[nty[i]], 1);
}

__global__ void k_toff() {
    if (threadIdx.x == 0) {
        int s = 0;
        for (int t = 0; t < NTYPE; t++) { g_tcur[t] = s; s += g_tcnt[t]; }
    }
}

__global__ void k_tfill(const int* __restrict__ nty) {
    int i = blockIdx.x * blockDim.x + threadIdx.x;
    if (i < NN) {
        int t = nty[i];
        int pos = atomicAdd(&g_tcur[t], 1);
        g_torder[pos] = (unsigned)i | ((unsigned)t << 20);
    } else if (i < NPAD) {
        g_torder[i] = (unsigned)(NN - 1) | (3u << 20);   // padding: safe node, max type
    }
}

// ---------------- encoder: per-type 2-layer MLP, 64-node type-sorted tiles ----------------
// W1 register-cached (type-sorted blocks -> <=2 reloads); occupancy 2 CTAs/SM.
#define ENC_SMEM_BYTES (104192)
__global__ __launch_bounds__(256, 2) void k_enc(
    const int* __restrict__ z, const float* __restrict__ sd,
    const float* __restrict__ dff, const float* __restrict__ cond,
    const float* __restrict__ mult,
    const float* __restrict__ zemb,
    const float* __restrict__ W1, const float* __restrict__ b1,
    const float* __restrict__ W2, const float* __restrict__ b2)
{
    extern __shared__ __align__(16) float sm[];
    float2* sw2i = (float2*)sm;            // [0, 16384) floats: interleaved W2 (one type)
    float*  sh1  = sm + 16384;             // [16384, 24576): 64 x 128
    float*  sraw = sm + 24576;             // [24576, 25856): 64 x 20
    int*    stype = (int*)(sm + 25856);    // 64
    int*    snode = stype + 64;            // 64
    int*    sz    = snode + 64;            // 64

    int tid = threadIdx.x;
    int n0 = blockIdx.x * 64;

    if (tid < 64) {
        unsigned v = g_torder[n0 + tid];
        int node = v & 0xFFFFF;
        snode[tid] = node;
        stype[tid] = v >> 20;
        sz[tid]    = z[node];
        sraw[tid * INDIM + 16] = sd[node];
        sraw[tid * INDIM + 17] = dff[node];
        sraw[tid * INDIM + 18] = cond[node];
        sraw[tid * INDIM + 19] = mult[node];
    }
    __syncthreads();
    for (int i = tid; i < 64 * FEAT; i += 256) {
        int li = i / FEAT, k = i % FEAT;
        sraw[li * INDIM + k] = zemb[sz[li] * FEAT + k];
    }
    __syncthreads();

    // phase B: h1 = relu(raw @ W1[t] + b1[t]); W1 column cached in 20 regs per thread
    {
        int c = tid & 127, half = tid >> 7;
        float w1r[INDIM];
        float b1r = 0.f;
        int curt = -1;
        for (int i = half; i < 64; i += 2) {
            int t = stype[i];
            if (t != curt) {
                curt = t;
                #pragma unroll
                for (int k = 0; k < INDIM; k++)
                    w1r[k] = __ldg(&W1[(t * INDIM + k) * HID + c]);
                b1r = __ldg(&b1[t * HID + c]);
            }
            float acc = b1r;
            #pragma unroll
            for (int k = 0; k < INDIM; k++)
                acc += sraw[i * INDIM + k] * w1r[k];
            sh1[i * HID + c] = fmaxf(acc, 0.f);
        }
    }

    // phase C: x = h1 @ W2[t] + b2[t], f32x2 engine; typically one type pass per block
    int lane = tid & 31, w = tid >> 5, c0 = lane * 4;
    int nodebase = w * 8;
    int tmin = stype[0], tmax = stype[63];
    for (int t = tmin; t <= tmax; t++) {
        __syncthreads();   // sh1 ready / previous pass done reading sw2i
        const float* W2t = W2 + (size_t)t * HID * HID;
        for (int i = tid; i < 2048; i += 256) {
            int kp = i >> 5, cg = i & 31;
            float4 a = *(const float4*)&W2t[(2 * kp) * HID + cg * 4];
            float4 b = *(const float4*)&W2t[(2 * kp + 1) * HID + cg * 4];
            float2* base = &sw2i[kp * 128];
            *(float4*)&base[cg * 2]      = make_float4(a.x, b.x, a.y, b.y);
            *(float4*)&base[64 + cg * 2] = make_float4(a.z, b.z, a.w, b.w);
        }
        __syncthreads();

        unsigned long long acc[8][4];
        {
            unsigned long long c0v = packlo(__ldg(&b2[t * HID + c0 + 0]));
            unsigned long long c1v = packlo(__ldg(&b2[t * HID + c0 + 1]));
            unsigned long long c2v = packlo(__ldg(&b2[t * HID + c0 + 2]));
            unsigned long long c3v = packlo(__ldg(&b2[t * HID + c0 + 3]));
            #pragma unroll
            for (int n = 0; n < 8; n++) {
                acc[n][0] = c0v; acc[n][1] = c1v; acc[n][2] = c2v; acc[n][3] = c3v;
            }
        }
        #pragma unroll 4
        for (int c4 = 0; c4 < 32; c4++) {
            const float2* rA = &sw2i[(2 * c4) * 128];
            const float2* rB = &sw2i[(2 * c4 + 1) * 128];
            ulonglong2 a0 = *(const ulonglong2*)&rA[lane * 2];
            ulonglong2 a1 = *(const ulonglong2*)&rA[64 + lane * 2];
            ulonglong2 b0 = *(const ulonglong2*)&rB[lane * 2];
            ulonglong2 b1 = *(const ulonglong2*)&rB[64 + lane * 2];
            #pragma unroll
            for (int n = 0; n < 8; n++) {
                ulonglong2 xq = *(const ulonglong2*)&sh1[(nodebase + n) * HID + c4 * 4];
                ffma2(acc[n][0], xq.x, a0.x);
                ffma2(acc[n][1], xq.x, a0.y);
                ffma2(acc[n][2], xq.x, a1.x);
                ffma2(acc[n][3], xq.x, a1.y);
                ffma2(acc[n][0], xq.y, b0.x);
                ffma2(acc[n][1], xq.y, b0.y);
                ffma2(acc[n][2], xq.y, b1.x);
                ffma2(acc[n][3], xq.y, b1.y);
            }
        }
        #pragma unroll
        for (int n = 0; n < 8; n++) {
            int i = nodebase + n;
            if (stype[i] == t && n0 + i < NN) {
                float4 o = make_float4(pairsum(acc[n][0]), pairsum(acc[n][1]),
                                       pairsum(acc[n][2]), pairsum(acc[n][3]));
                *(float4*)&g_x[(size_t)snode[i] * HID + c0] = o;
            }
        }
    }
}

// ---------------- CSR scan ----------------
__global__ __launch_bounds__(1024) void k_scan1() {
    __shared__ int s[1024];
    int b = blockIdx.x, tid = threadIdx.x;
    int i = b * 1024 + tid;
    int v = (i < NN) ? g_deg[i] : 0;
    s[tid] = v;
    __syncthreads();
    for (int off = 1; off < 1024; off <<= 1) {
        int t = (tid >= off) ? s[tid - off] : 0;
        __syncthreads();
        s[tid] += t;
        __syncthreads();
    }
    if (i < NN) g_off[i] = s[tid] - v;
    if (tid == 1023) g_bsum[b] = s[1023];
}

__global__ void k_scan2() {
    if (threadIdx.x == 0) {
        int s = 0;
        for (int b = 0; b < NB_SCAN; b++) { int v = g_bsum[b]; g_bsum[b] = s; s += v; }
    }
}

__global__ __launch_bounds__(1024) void k_scan3() {
    int b = blockIdx.x, i = b * 1024 + threadIdx.x;
    if (i < NN) {
        int val = g_off[i] + g_bsum[b];
        g_off[i] = val;
        g_cur[i] = val;
    }
    if (i == NN) g_off[NN] = EE;
}

__global__ void k_fill(const int* __restrict__ src, const int* __restrict__ dst,
                       const int* __restrict__ et) {
    int e = blockIdx.x * blockDim.x + threadIdx.x;
    if (e < EE) {
        int d = dst[e];
        int pos = atomicAdd(&g_cur[d], 1);
        g_eidx[pos] = (unsigned)src[e] | ((unsigned)et[e] << 17);
    }
}

// ---------------- weight prep: transpose + bf16 hi/lo split + swizzled images ----------------
__global__ void k_wprep(const float* __restrict__ relW, const float* __restrict__ linW) {
    int b = blockIdx.x;                  // 0..7  -> (layer, m)
    int l = b >> 2, m = b & 3;
    const float* W = (m < 3) ? relW + ((size_t)l * 3 + m) * 16384
                             : linW + (size_t)l * 16384;
    unsigned char* img = g_wimg + ((size_t)b << 16);
    for (int idx = threadIdx.x; idx < 2048; idx += blockDim.x) {
        int n = idx >> 4, ch = idx & 15;
        unsigned hi[4], lo[4];
        #pragma unroll
        for (int j = 0; j < 4; j++) {
            float v0 = W[(ch * 8 + 2 * j) * HID + n];
            float v1 = W[(ch * 8 + 2 * j + 1) * HID + n];
            unsigned h0 = b16(v0), h1 = b16(v1);
            hi[j] = h0 | (h1 << 16);
            lo[j] = b16(v0 - b16f(h0)) | (b16(v1 - b16f(h1)) << 16);
        }
        unsigned off = swzoff(n, ch);
        *(uint4*)(img + off)         = make_uint4(hi[0], hi[1], hi[2], hi[3]);
        *(uint4*)(img + 32768 + off) = make_uint4(lo[0], lo[1], lo[2], lo[3]);
    }
}

// ---------------- gather: per-node per-relation sums (CSR, unroll-4 for MLP) ----------------
__device__ __forceinline__ void acc_rel(float4& a0, float4& a1, float4& a2,
                                        unsigned r, float4 xv) {
    if (r == 0)      { a0.x += xv.x; a0.y += xv.y; a0.z += xv.z; a0.w += xv.w; }
    else if (r == 1) { a1.x += xv.x; a1.y += xv.y; a1.z += xv.z; a1.w += xv.w; }
    else             { a2.x += xv.x; a2.y += xv.y; a2.z += xv.z; a2.w += xv.w; }
}

__global__ __launch_bounds__(256) void k_gather() {
    int wid = threadIdx.x >> 5, lane = threadIdx.x & 31;
    int node = blockIdx.x * 8 + wid;                    // NN % 8 == 0
    int rs = g_off[node], re = g_off[node + 1];
    int cb = lane * 4;
    float4 a0 = make_float4(0.f, 0.f, 0.f, 0.f);
    float4 a1 = a0, a2 = a0;
    for (int base = rs; base < re; base += 32) {
        int n = min(32, re - base);
        unsigned ep = (base + lane < re) ? g_eidx[base + lane] : 0u;
        int j = 0;
        #pragma unroll 1
        for (; j + 4 <= n; j += 4) {
            unsigned v0 = __shfl_sync(0xffffffffu, ep, j);
            unsigned v1 = __shfl_sync(0xffffffffu, ep, j + 1);
            unsigned v2 = __shfl_sync(0xffffffffu, ep, j + 2);
            unsigned v3 = __shfl_sync(0xffffffffu, ep, j + 3);
            float4 x0 = *(const float4*)&g_x[(size_t)(v0 & 0x1FFFF) * HID + cb];
            float4 x1 = *(const float4*)&g_x[(size_t)(v1 & 0x1FFFF) * HID + cb];
            float4 x2 = *(const float4*)&g_x[(size_t)(v2 & 0x1FFFF) * HID + cb];
            float4 x3 = *(const float4*)&g_x[(size_t)(v3 & 0x1FFFF) * HID + cb];
            acc_rel(a0, a1, a2, v0 >> 17, x0);
            acc_rel(a0, a1, a2, v1 >> 17, x1);
            acc_rel(a0, a1, a2, v2 >> 17, x2);
            acc_rel(a0, a1, a2, v3 >> 17, x3);
        }
        for (; j < n; j++) {
            unsigned v = __shfl_sync(0xffffffffu, ep, j);
            float4 xv = *(const float4*)&g_x[(size_t)(v & 0x1FFFF) * HID + cb];
            acc_rel(a0, a1, a2, v >> 17, xv);
        }
    }
    float inv = 1.f / (float)max(re - rs, 1);
    size_t o = (size_t)node * HID + cb;
    *(float4*)&g_y[0][o] = make_float4(a0.x * inv, a0.y * inv, a0.z * inv, a0.w * inv);
    *(float4*)&g_y[1][o] = make_float4(a1.x * inv, a1.y * inv, a1.z * inv, a1.w * inv);
    *(float4*)&g_y[2][o] = make_float4(a2.x * inv, a2.y * inv, a2.z * inv, a2.w * inv);
}

// ---------------- mma.sync fused 4-GEMM (split-bf16) + bias + LayerNorm ----------------
// A tile for step m+1 prefetched into registers while step m's MMAs run.
#define GEMM_SMEM_BYTES (131072)
__global__ __launch_bounds__(256) void k_gemm(
    int layer, const float* __restrict__ linb,
    const float* __restrict__ lng, const float* __restrict__ lnb)
{
    extern __shared__ __align__(16) unsigned char dsm[];
    __shared__ float s_linb[HID], s_lng[HID], s_lnb[HID];

    unsigned char* AH = dsm;              // 32KB
    unsigned char* AL = dsm + 32768;      // 32KB
    unsigned char* BH = dsm + 65536;      // 32KB (hi) + 32KB (lo) contiguous

    int tid = threadIdx.x, lane = tid & 31, w = tid >> 5;
    int n0 = blockIdx.x * 128;

    if (tid < HID) { s_linb[tid] = linb[tid]; s_lng[tid] = lng[tid]; s_lnb[tid] = lnb[tid]; }

    unsigned aHB = smem_u32(AH), aLB = smem_u32(AL);
    unsigned bHB = smem_u32(BH), bLB = bHB + 32768;

    int g = lane >> 3, r = lane & 7;
    int rowA = 16 * w + ((g & 1) << 3) + r;
    int achS = g >> 1;
    int nOff = ((g >> 1) << 3) + r;
    int bchS = g & 1;

    float acc[16][4];
    #pragma unroll
    for (int t = 0; t < 16; t++)
        acc[t][0] = acc[t][1] = acc[t][2] = acc[t][3] = 0.f;

    int arow = tid >> 1, ahalf = tid & 1;

    // prefetch A tile for m=0
    float4 pref[16];
    {
        const float4* asrc = (const float4*)(g_y[0] + (size_t)(n0 + arow) * HID + ahalf * 64);
        #pragma unroll
        for (int j = 0; j < 16; j++) pref[j] = asrc[j];
    }

    #pragma unroll 1
    for (int m = 0; m < 4; m++) {
        __syncthreads();    // all warps done reading smem from previous step
        // stage B: linear 64KB copy of pre-swizzled hi+lo image
        {
            const uint4* bsrc = (const uint4*)(g_wimg + (((size_t)layer * 4 + m) << 16));
            uint4* bdst = (uint4*)BH;
            #pragma unroll
            for (int i = 0; i < 16; i++) bdst[tid + 256 * i] = bsrc[tid + 256 * i];
        }
        // convert prefetched A regs -> bf16 hi/lo swizzled smem
        #pragma unroll
        for (int c = 0; c < 8; c++) {
            float4 v0 = pref[2 * c], v1 = pref[2 * c + 1];
            unsigned h0 = b16(v0.x), h1 = b16(v0.y), h2 = b16(v0.z), h3 = b16(v0.w);
            unsigned h4 = b16(v1.x), h5 = b16(v1.y), h6 = b16(v1.z), h7 = b16(v1.w);
            unsigned off = swzoff(arow, ahalf * 8 + c);
            *(uint4*)(AH + off) = make_uint4(h0 | (h1 << 16), h2 | (h3 << 16),
                                             h4 | (h5 << 16), h6 | (h7 << 16));
            unsigned l0 = b16(v0.x - b16f(h0)), l1 = b16(v0.y - b16f(h1));
            unsigned l2 = b16(v0.z - b16f(h2)), l3 = b16(v0.w - b16f(h3));
            unsigned l4 = b16(v1.x - b16f(h4)), l5 = b16(v1.y - b16f(h5));
            unsigned l6 = b16(v1.z - b16f(h6)), l7 = b16(v1.w - b16f(h7));
            *(uint4*)(AL + off) = make_uint4(l0 | (l1 << 16), l2 | (l3 << 16),
                                             l4 | (l5 << 16), l6 | (l7 << 16));
        }
        __syncthreads();
        // issue next A-tile loads now; latency hides under the MMA block below
        if (m < 3) {
            const float* inp = (m == 0) ? g_y[1] : (m == 1) ? g_y[2] : g_x;
            const float4* asrc = (const float4*)(inp + (size_t)(n0 + arow) * HID + ahalf * 64);
            #pragma unroll
            for (int j = 0; j < 16; j++) pref[j] = asrc[j];
        }

        #pragma unroll 2
        for (int ks = 0; ks < 8; ks++) {
            unsigned aoff = swzoff(rowA, 2 * ks + achS);
            unsigned ah0, ah1, ah2, ah3, al0, al1, al2, al3;
            LDSM_X4(ah0, ah1, ah2, ah3, aHB + aoff);
            LDSM_X4(al0, al1, al2, al3, aLB + aoff);
            #pragma unroll
            for (int t = 0; t < 8; t++) {
                int nB = 16 * t + nOff;
                unsigned boff = swzoff(nB, 2 * ks + bchS);
                unsigned bh0, bh1, bh2, bh3, bl0, bl1, bl2, bl3;
                LDSM_X4(bh0, bh1, bh2, bh3, bHB + boff);
                LDSM_X4(bl0, bl1, bl2, bl3, bLB + boff);
                MMA16816(acc[2 * t],     ah0, ah1, ah2, ah3, bh0, bh1);
                MMA16816(acc[2 * t],     al0, al1, al2, al3, bh0, bh1);
                MMA16816(acc[2 * t],     ah0, ah1, ah2, ah3, bl0, bl1);
                MMA16816(acc[2 * t + 1], ah0, ah1, ah2, ah3, bh2, bh3);
                MMA16816(acc[2 * t + 1], al0, al1, al2, al3, bh2, bh3);
                MMA16816(acc[2 * t + 1], ah0, ah1, ah2, ah3, bl2, bl3);
            }
        }
    }

    // epilogue: bias + per-row LayerNorm + write g_x
    {
        int q = lane & 3;
        int r0 = n0 + 16 * w + (lane >> 2), r1 = r0 + 8;
        float s0 = 0.f, s1 = 0.f;
        #pragma unroll
        for (int t = 0; t < 16; t++) {
            int c = 8 * t + 2 * q;
            float bx = s_linb[c], by = s_linb[c + 1];
            acc[t][0] += bx; acc[t][1] += by;
            acc[t][2] += bx; acc[t][3] += by;
            s0 += acc[t][0] + acc[t][1];
            s1 += acc[t][2] + acc[t][3];
        }
        s0 += __shfl_xor_sync(0xffffffffu, s0, 1);
        s0 += __shfl_xor_sync(0xffffffffu, s0, 2);
        s1 += __shfl_xor_sync(0xffffffffu, s1, 1);
        s1 += __shfl_xor_sync(0xffffffffu, s1, 2);
        float mu0 = s0 * (1.f / HID), mu1 = s1 * (1.f / HID);
        float v0 = 0.f, v1 = 0.f;
        #pragma unroll
        for (int t = 0; t < 16; t++) {
            float d0 = acc[t][0] - mu0, d1 = acc[t][1] - mu0;
            float d2 = acc[t][2] - mu1, d3 = acc[t][3] - mu1;
            v0 += d0 * d0 + d1 * d1;
            v1 += d2 * d2 + d3 * d3;
        }
        v0 += __shfl_xor_sync(0xffffffffu, v0, 1);
        v0 += __shfl_xor_sync(0xffffffffu, v0, 2);
        v1 += __shfl_xor_sync(0xffffffffu, v1, 1);
        v1 += __shfl_xor_sync(0xffffffffu, v1, 2);
        float rs0 = rsqrtf(v0 * (1.f / HID) + LNEPS);
        float rs1 = rsqrtf(v1 * (1.f / HID) + LNEPS);
        #pragma unroll
        for (int t = 0; t < 16; t++) {
            int c = 8 * t + 2 * q;
            float gx = s_lng[c], gy = s_lng[c + 1];
            float bx = s_lnb[c], by = s_lnb[c + 1];
            if (r0 < NN) {
                float2 o0 = make_float2((acc[t][0] - mu0) * rs0 * gx + bx,
                                        (acc[t][1] - mu0) * rs0 * gy + by);
                *(float2*)&g_x[(size_t)r0 * HID + c] = o0;
            }
            if (r1 < NN) {
                float2 o1 = make_float2((acc[t][2] - mu1) * rs1 * gx + bx,
                                        (acc[t][3] - mu1) * rs1 * gy + by);
                *(float2*)&g_x[(size_t)r1 * HID + c] = o1;
            }
        }
    }
}

// ---------------- pooling + regressor ----------------
__global__ __launch_bounds__(256) void k_pool() {
    __shared__ float4 spart[256];
    int lane = threadIdx.x & 31, w = threadIdx.x >> 5;
    float4 acc = make_float4(0.f, 0.f, 0.f, 0.f);
    for (int node = blockIdx.x * 8 + w; node < NN; node += gridDim.x * 8) {
        float4 v = *(const float4*)&g_x[(size_t)node * HID + lane * 4];
        acc.x += v.x; acc.y += v.y; acc.z += v.z; acc.w += v.w;
    }
    spart[threadIdx.x] = acc;
    __syncthreads();
    if (w == 0) {
        float4 s = spart[lane];
        #pragma unroll
        for (int q = 1; q < 8; q++) {
            float4 v = spart[q * 32 + lane];
            s.x += v.x; s.y += v.y; s.z += v.z; s.w += v.w;
        }
        atomicAdd(&g_pooled[lane * 4 + 0], s.x);
        atomicAdd(&g_pooled[lane * 4 + 1], s.y);
        atomicAdd(&g_pooled[lane * 4 + 2], s.z);
        atomicAdd(&g_pooled[lane * 4 + 3], s.w);
    }
}

__global__ void k_final(const float* __restrict__ regW,
                        const float* __restrict__ regb, float* __restrict__ out)
{
    int lane = threadIdx.x;
    float4 p = *(const float4*)&g_pooled[lane * 4];
    float4 w = *(const float4*)&regW[lane * 4];
    float s = p.x * w.x + p.y * w.y + p.z * w.z + p.w * w.w;
    #pragma unroll
    for (int o = 16; o; o >>= 1) s += __shfl_xor_sync(0xffffffffu, s, o);
    if (lane == 0) out[0] = s * (1.f / NN) + regb[0];
}

// ---------------- host launcher ----------------
extern "C" void kernel_launch(void* const* d_in, const int* in_sizes, int n_in,
                              void* d_out, int out_size)
{
    const int*   z    = (const int*)  d_in[0];
    const float* sd   = (const float*)d_in[1];
    const float* dff  = (const float*)d_in[2];
    const float* cond = (const float*)d_in[3];
    const float* mult = (const float*)d_in[4];
    const int*   nty  = (const int*)  d_in[5];
    const int*   ei   = (const int*)  d_in[6];
    const int*   et   = (const int*)  d_in[7];
    const float* zemb = (const float*)d_in[8];
    const float* eW1  = (const float*)d_in[9];
    const float* eb1  = (const float*)d_in[10];
    const float* eW2  = (const float*)d_in[11];
    const float* eb2  = (const float*)d_in[12];
    const float* linW = (const float*)d_in[13];
    const float* linb = (const float*)d_in[14];
    const float* relW = (const float*)d_in[15];
    const float* lng  = (const float*)d_in[16];
    const float* lnb  = (const float*)d_in[17];
    const float* regW = (const float*)d_in[18];
    const float* regb = (const float*)d_in[19];
    const int* src = ei, * dst = ei + EE;

    cudaFuncSetAttribute(k_enc, cudaFuncAttributeMaxDynamicSharedMemorySize, ENC_SMEM_BYTES);
    cudaFuncSetAttribute(k_gemm, cudaFuncAttributeMaxDynamicSharedMemorySize, GEMM_SMEM_BYTES);

    // zero histogram buffers via async memset (graph-capturable, no launches)
    void *p_deg = nullptr, *p_tcnt = nullptr, *p_pooled = nullptr;
    cudaGetSymbolAddress(&p_deg, g_deg);
    cudaGetSymbolAddress(&p_tcnt, g_tcnt);
    cudaGetSymbolAddress(&p_pooled, g_pooled);
    cudaMemsetAsync(p_deg, 0, (size_t)NN * sizeof(int));
    cudaMemsetAsync(p_tcnt, 0, NTYPE * sizeof(int));
    cudaMemsetAsync(p_pooled, 0, HID * sizeof(float));

    // type bucketing + encoder first (k_enc at kernel-launch index 3 for ncu)
    k_hist<<<(EE + 255) / 256, 256>>>(dst, nty);
    k_toff<<<1, 32>>>();
    k_tfill<<<(NPAD + 255) / 256, 256>>>(nty);
    k_enc<<<NPAD / 64, 256, ENC_SMEM_BYTES>>>(z, sd, dff, cond, mult, zemb,
                                              eW1, eb1, eW2, eb2);
    // CSR + weight images
    k_scan1<<<NB_SCAN, 1024>>>();
    k_scan2<<<1, 32>>>();
    k_scan3<<<NB_SCAN, 1024>>>();
    k_fill<<<(EE + 255) / 256, 256>>>(src, dst, et);
    k_wprep<<<8, 256>>>(relW, linW);

    // GNN layers
    for (int l = 0; l < 2; l++) {
        k_gather<<<NN / 8, 256>>>();
        k_gemm<<<NPAD / 128, 256, GEMM_SMEM_BYTES>>>(l, linb + (size_t)l * HID,
                                                     lng + (size_t)l * HID,
                                                     lnb + (size_t)l * HID);
    }
    k_pool<<<512, 256>>>();
    k_final<<<1, 32>>>(regW, regb, (float*)d_out);
}